// round 12
// baseline (speedup 1.0000x reference)
#include <cuda_runtime.h>
#include <cuda_bf16.h>
#include <cstdint>

#define NNODES 50000
#define NEDGE  1000000
#define DIN0   2000
#define EPS_BN 1e-5f
#define LSLOPE 0.01f
#define NN3    150000
#define SCAN_BLOCKS 147
#define GA_BLK 6250   /* (NNODES+7)/8 */
#define GB_SM  391    /* (NNODES+127)/128 */
#define GN_BLK 3907   /* (NNODES*20+255)/256 */

// qkv row layout (80 floats): [ q(0..19) | k0 v0 k1 v1 .. k19 v19 (20..59) | skip(60..79) ]

// ------------------------- scratch (device globals, zero-init) -------------
__device__ float g_qkvA[NNODES * 80];
__device__ float g_qkvB[NNODES * 80];
__device__ float g_qkvC[NNODES * 80];
__device__ float g_preA[NNODES * 20];
__device__ float g_preB[NNODES * 20];
__device__ float g_preC[NNODES * 20];
__device__ float g_fc[NNODES * 100];
__device__ float g_stats[15 * 40];
__device__ __nv_bfloat16 g_wt_hi[2000 * 160];
__device__ __nv_bfloat16 g_wt_lo[2000 * 160];
// CSR scratch
__device__ int g_cnt[NN3];
__device__ int g_off[NN3 + 1];
__device__ int g_cur[NN3];
__device__ int g_csr[3 * NEDGE];
__device__ int g_partraw[SCAN_BLOCKS];
__device__ int g_part[SCAN_BLOCKS];

// ------------------------- helpers -------------------------
__device__ __forceinline__ unsigned long long ffma2(unsigned long long a,
                                                    unsigned long long b,
                                                    unsigned long long c) {
    unsigned long long d;
    asm("fma.rn.f32x2 %0, %1, %2, %3;" : "=l"(d) : "l"(a), "l"(b), "l"(c));
    return d;
}
__device__ __forceinline__ unsigned long long pack2(float lo, float hi) {
    unsigned long long r;
    asm("mov.b64 %0, {%1, %2};" : "=l"(r) : "f"(lo), "f"(hi));
    return r;
}
__device__ __forceinline__ uint32_t smem_u32(const void* p) {
    uint32_t a;
    asm("{ .reg .u64 t; cvta.to.shared.u64 t, %1; cvt.u32.u64 %0, t; }"
        : "=r"(a) : "l"(p));
    return a;
}
__device__ __forceinline__ uint32_t packbf2(float a, float b, float* lo_a, float* lo_b) {
    __nv_bfloat16 ha = __float2bfloat16(a), hb = __float2bfloat16(b);
    *lo_a = a - __bfloat162float(ha);
    *lo_b = b - __bfloat162float(hb);
    __nv_bfloat162 p; p.x = ha; p.y = hb;
    return *(uint32_t*)&p;
}
__device__ __forceinline__ uint32_t packbf2s(float a, float b) {
    __nv_bfloat162 p; p.x = __float2bfloat16(a); p.y = __float2bfloat16(b);
    return *(uint32_t*)&p;
}
// logical qkv column (0..79) -> interleaved position
__device__ __forceinline__ int qkvpos(int c) {
    if (c < 20) return c;
    if (c < 40) return 2 * c - 20;   // k_c -> 20+2c
    if (c < 60) return 2 * c - 59;   // v_c -> 21+2c
    return c;
}

// ------------------------- CSR build -------------------------
__global__ void zero_all() {
    int i = blockIdx.x * blockDim.x + threadIdx.x;
    if (i < NN3) g_cnt[i] = 0;
    if (i < 15 * 40) g_stats[i] = 0.f;
}
__global__ void hist_kernel(const int* __restrict__ e0, const int* __restrict__ e1,
                            const int* __restrict__ e2) {
    int i = blockIdx.x * blockDim.x + threadIdx.x;
    if (i >= 3 * NEDGE) return;
    int set = i / NEDGE, e = i - set * NEDGE;
    const int* ei = (set == 0) ? e0 : ((set == 1) ? e1 : e2);
    atomicAdd(&g_cnt[set * NNODES + ei[NEDGE + e]], 1);
}
__global__ void __launch_bounds__(1024) scanA() {
    int gid = blockIdx.x * 1024 + threadIdx.x;
    int v = (gid < NN3) ? g_cnt[gid] : 0;
#pragma unroll
    for (int o = 16; o; o >>= 1) v += __shfl_xor_sync(~0u, v, o);
    __shared__ int sw[32];
    if ((threadIdx.x & 31) == 0) sw[threadIdx.x >> 5] = v;
    __syncthreads();
    if (threadIdx.x < 32) {
        int t = sw[threadIdx.x];
#pragma unroll
        for (int o = 16; o; o >>= 1) t += __shfl_xor_sync(~0u, t, o);
        if (threadIdx.x == 0) g_partraw[blockIdx.x] = t;
    }
}
__global__ void scanB() {
    __shared__ int sp[SCAN_BLOCKS + 1];
    int tid = threadIdx.x;
    if (tid < SCAN_BLOCKS) sp[tid + 1] = g_partraw[tid];
    if (tid == 0) sp[0] = 0;
    __syncthreads();
    if (tid == 0)
        for (int b = 1; b <= SCAN_BLOCKS; b++) sp[b] += sp[b - 1];
    __syncthreads();
    if (tid < SCAN_BLOCKS) g_part[tid] = sp[tid];
}
__global__ void __launch_bounds__(1024) scanC() {
    __shared__ int sdat[1024];
    int tid = threadIdx.x;
    int gid = blockIdx.x * 1024 + tid;
    int v = (gid < NN3) ? g_cnt[gid] : 0;
    sdat[tid] = v;
    __syncthreads();
    for (int o = 1; o < 1024; o <<= 1) {
        int t = (tid >= o) ? sdat[tid - o] : 0;
        __syncthreads();
        sdat[tid] += t;
        __syncthreads();
    }
    int excl = sdat[tid] - v + g_part[blockIdx.x];
    if (gid < NN3) { g_off[gid] = excl; g_cur[gid] = excl; }
    if (gid == 0) g_off[NN3] = 3 * NEDGE;
}
__global__ void scatter_kernel(const int* __restrict__ e0, const int* __restrict__ e1,
                               const int* __restrict__ e2) {
    int i = blockIdx.x * blockDim.x + threadIdx.x;
    if (i >= 3 * NEDGE) return;
    int set = i / NEDGE, e = i - set * NEDGE;
    const int* ei = (set == 0) ? e0 : ((set == 1) ? e1 : e2);
    int s = ei[e], d = ei[NEDGE + e];
    int pos = atomicAdd(&g_cur[set * NNODES + d], 1);
    g_csr[pos] = s;
}

// ------------- W split+transpose with kv-interleave column permutation -----
__global__ void conv_w(const float* __restrict__ W1, const float* __restrict__ W2) {
    int idx = blockIdx.x * blockDim.x + threadIdx.x;
    if (idx >= 2000 * 160) return;
    int k = idx / 160, n = idx - k * 160;
    const float* Wsrc = (n < 80) ? W1 : W2;
    int nn = (n < 80) ? n : n - 80;
    int s = nn / 20, o = nn % 20;
    float w = Wsrc[((size_t)s * 2000 + k) * 20 + o];
    __nv_bfloat16 h = __float2bfloat16(w);
    int nperm = ((n < 80) ? 0 : 80) + qkvpos(nn);
    g_wt_hi[(size_t)k * 160 + nperm] = h;
    g_wt_lo[(size_t)k * 160 + nperm] = __float2bfloat16(w - __bfloat162float(h));
}

// ------------------------- big GEMM via mma.sync bf16-split ----------------
#define SA_STRIDE 168
#define SB_STRIDE 168

__global__ void __launch_bounds__(256, 2)
gemm_big_mma(const float* __restrict__ A,
             const float* __restrict__ b1, const float* __restrict__ b2,
             float* __restrict__ outA, float* __restrict__ outB) {
    extern __shared__ __align__(16) char dsm[];
    __nv_bfloat16* sA = (__nv_bfloat16*)dsm;
    __nv_bfloat16* sB = (__nv_bfloat16*)(dsm + 128 * SA_STRIDE * 2);
    __shared__ float s_bias[160];

    const int tid = threadIdx.x, wid = tid >> 5, lane = tid & 31;
    const int rowbase = blockIdx.x * 128;
    if (tid < 160) {
        int g = tid / 80, c = tid % 80;
        float bv = (g == 0) ? b1[c] : b2[c];
        s_bias[g * 80 + qkvpos(c)] = bv;
    }

    float acc[20][4];
#pragma unroll
    for (int t = 0; t < 20; t++)
#pragma unroll
        for (int i = 0; i < 4; i++) acc[t][i] = 0.f;

    const int r_in = lane & 7, blkb = (lane >> 3) & 1, kh = (lane >> 4) & 1;
    const uint32_t aBase =
        smem_u32(sA) + (uint32_t)((wid * 16 + blkb * 8 + r_in) * SA_STRIDE + kh * 8) * 2;
    const uint32_t bBase2 = smem_u32(sB) + (uint32_t)((lane & 15) * SB_STRIDE) * 2;
    const uint32_t bBase4 = smem_u32(sB) + (uint32_t)(lane * SB_STRIDE) * 2;

    const int a0off[7] = {0, 32, 64, 16, 48, 80, 112};
    const int a1off[7] = {16, 48, 0, 32, 64, 96, 128};
    const int browt[7] = {0, 32, 64, 96, 128, 0, 32};

    for (int ch = 0; ch < 25; ch++) {
        const int k0 = ch * 80;
#pragma unroll
        for (int it = 0; it < 13; it++) {
            int q = tid + it * 256;
            if (q < 3200) {
                int row = q / 20, c16 = q - row * 20;
                int kk = (row >= 80) ? row - 80 : row;
                const __nv_bfloat16* src =
                    ((row >= 80) ? g_wt_lo : g_wt_hi) + (size_t)(k0 + kk) * 160 + c16 * 8;
                uint32_t dst = smem_u32(sB) + (uint32_t)(row * SB_STRIDE + c16 * 8) * 2;
                asm volatile("cp.async.ca.shared.global [%0], [%1], 16;"
                             :: "r"(dst), "l"(src));
            }
        }
        asm volatile("cp.async.commit_group;" ::: "memory");
#pragma unroll
        for (int it = 0; it < 10; it++) {
            int q = tid + it * 256;
            int r = q / 20, f = q - r * 20;
            int row = rowbase + r;
            float4 v = (row < NNODES)
                           ? *(const float4*)(A + (size_t)row * 2000 + k0 + f * 4)
                           : make_float4(0.f, 0.f, 0.f, 0.f);
            float l0, l1, l2, l3;
            uint32_t h0 = packbf2(v.x, v.y, &l0, &l1);
            uint32_t h1 = packbf2(v.z, v.w, &l2, &l3);
            uint32_t p0 = packbf2s(l0, l1), p1 = packbf2s(l2, l3);
            int k = f * 4;
            __nv_bfloat16* rp = sA + r * SA_STRIDE;
            *(uint32_t*)(rp + k) = h0;
            *(uint32_t*)(rp + k + 2) = h1;
            *(uint32_t*)(rp + 80 + k) = p0;
            *(uint32_t*)(rp + 82 + k) = p1;
        }
        asm volatile("cp.async.wait_group 0;" ::: "memory");
        __syncthreads();
#pragma unroll
        for (int jp = 0; jp < 7; jp++) {
            uint32_t a0, a1, a2, a3, c0, c1, c2, c3;
            asm volatile(
                "ldmatrix.sync.aligned.m8n8.x4.shared.b16 {%0,%1,%2,%3}, [%4];"
                : "=r"(a0), "=r"(a1), "=r"(a2), "=r"(a3)
                : "r"(aBase + (uint32_t)a0off[jp] * 2));
            asm volatile(
                "ldmatrix.sync.aligned.m8n8.x4.shared.b16 {%0,%1,%2,%3}, [%4];"
                : "=r"(c0), "=r"(c1), "=r"(c2), "=r"(c3)
                : "r"(aBase + (uint32_t)a1off[jp] * 2));
            const uint32_t bb = bBase4 + (uint32_t)(browt[jp] * SB_STRIDE) * 2;
#pragma unroll
            for (int t = 0; t < 20; t++) {
                uint32_t b0, b1, b2, b3;
                asm volatile(
                    "ldmatrix.sync.aligned.m8n8.x4.trans.shared.b16 {%0,%1,%2,%3}, [%4];"
                    : "=r"(b0), "=r"(b1), "=r"(b2), "=r"(b3)
                    : "r"(bb + (uint32_t)t * 16));
                asm volatile(
                    "mma.sync.aligned.m16n8k16.row.col.f32.bf16.bf16.f32 "
                    "{%0,%1,%2,%3}, {%4,%5,%6,%7}, {%8,%9}, {%0,%1,%2,%3};"
                    : "+f"(acc[t][0]), "+f"(acc[t][1]), "+f"(acc[t][2]), "+f"(acc[t][3])
                    : "r"(a0), "r"(a1), "r"(a2), "r"(a3), "r"(b0), "r"(b1));
                asm volatile(
                    "mma.sync.aligned.m16n8k16.row.col.f32.bf16.bf16.f32 "
                    "{%0,%1,%2,%3}, {%4,%5,%6,%7}, {%8,%9}, {%0,%1,%2,%3};"
                    : "+f"(acc[t][0]), "+f"(acc[t][1]), "+f"(acc[t][2]), "+f"(acc[t][3])
                    : "r"(c0), "r"(c1), "r"(c2), "r"(c3), "r"(b2), "r"(b3));
            }
        }
        {
            uint32_t a0, a1, a2, a3;
            asm volatile(
                "ldmatrix.sync.aligned.m8n8.x4.shared.b16 {%0,%1,%2,%3}, [%4];"
                : "=r"(a0), "=r"(a1), "=r"(a2), "=r"(a3)
                : "r"(aBase + 144u * 2));
            const uint32_t bb = bBase2 + (uint32_t)(64 * SB_STRIDE) * 2;
#pragma unroll
            for (int t = 0; t < 20; t++) {
                uint32_t b0, b1;
                asm volatile(
                    "ldmatrix.sync.aligned.m8n8.x2.trans.shared.b16 {%0,%1}, [%2];"
                    : "=r"(b0), "=r"(b1)
                    : "r"(bb + (uint32_t)t * 16));
                asm volatile(
                    "mma.sync.aligned.m16n8k16.row.col.f32.bf16.bf16.f32 "
                    "{%0,%1,%2,%3}, {%4,%5,%6,%7}, {%8,%9}, {%0,%1,%2,%3};"
                    : "+f"(acc[t][0]), "+f"(acc[t][1]), "+f"(acc[t][2]), "+f"(acc[t][3])
                    : "r"(a0), "r"(a1), "r"(a2), "r"(a3), "r"(b0), "r"(b1));
            }
        }
        __syncthreads();
    }

    const int r0 = rowbase + wid * 16 + lane / 4;
    const int r1 = r0 + 8;
    const int cb = (lane & 3) * 2;
#pragma unroll
    for (int t = 0; t < 20; t++) {
        int col = t * 8 + cb;
        float* base = (col < 80) ? outA : outB;
        int cc = (col < 80) ? col : col - 80;
        float bia0 = s_bias[col], bia1 = s_bias[col + 1];
        if (r0 < NNODES)
            *(float2*)(base + (size_t)r0 * 80 + cc) =
                make_float2(acc[t][0] + bia0, acc[t][1] + bia1);
        if (r1 < NNODES)
            *(float2*)(base + (size_t)r1 * 80 + cc) =
                make_float2(acc[t][2] + bia0, acc[t][3] + bia1);
    }
}

// --------------- fused small GEMMs (+ optional bn_fc block range) ----------
__global__ void __launch_bounds__(256)
gemm_small3(const float* __restrict__ preA, const float* __restrict__ preB,
            const float* __restrict__ stX, const float* __restrict__ stY,
            const float* __restrict__ g1, const float* __restrict__ be1,
            const float* __restrict__ g2, const float* __restrict__ be2,
            const float* __restrict__ Wc3, const float* __restrict__ bc3,
            float* __restrict__ outC,
            const float* __restrict__ Wc1, const float* __restrict__ bc1,
            float* __restrict__ outA,
            const float* __restrict__ Wc2, const float* __restrict__ bc2,
            float* __restrict__ outB,
            int nsets,
            const float* __restrict__ bnPre, const float* __restrict__ bnStats,
            const float* __restrict__ bnG, const float* __restrict__ bnB,
            float* __restrict__ bnDst, int bnOff) {
    const int bnStart = nsets * GB_SM;
    if ((int)blockIdx.x >= bnStart) {
        int idx = (blockIdx.x - bnStart) * 256 + threadIdx.x;
        if (idx >= NNODES * 20) return;
        int n = idx / 20, c = idx % 20;
        const float invN = 1.f / (float)NNODES;
        float mu = bnStats[c] * invN;
        float var = bnStats[20 + c] * invN - mu * mu;
        float scv = bnG[c] * rsqrtf(var + EPS_BN);
        float v = (bnPre[idx] - mu) * scv + bnB[c];
        v = (v >= 0.f) ? v : LSLOPE * v;
        bnDst[(size_t)n * 100 + bnOff + c] = v;
        return;
    }
    const int set = blockIdx.x / GB_SM;
    const int bi = blockIdx.x - set * GB_SM;
    const bool swap = (set == 2);
    const float* preX = swap ? preB : preA;
    const float* preY = swap ? preA : preB;
    const float* statsX = swap ? stY : stX;
    const float* statsY = swap ? stX : stY;
    const float* gX = swap ? g2 : g1;
    const float* betX = swap ? be2 : be1;
    const float* gY = swap ? g1 : g2;
    const float* betY = swap ? be1 : be2;
    const float* W = (set == 0) ? Wc3 : ((set == 1) ? Wc1 : Wc2);
    const float* b = (set == 0) ? bc3 : ((set == 1) ? bc1 : bc2);
    float* out = (set == 0) ? outC : ((set == 1) ? outA : outB);

    __shared__ __align__(8) float sW[40][80];
    __shared__ float sb[80];
    __shared__ float sMu[40], sScv[40], sBeta[40];
    const int tid = threadIdx.x;
    for (int l = tid; l < 3200; l += 256) {
        int s = l / 800, rem = l % 800, k = rem / 20, o = rem % 20;
        sW[k][qkvpos(s * 20 + o)] = W[l];
    }
    if (tid < 80) sb[qkvpos(tid)] = b[tid];
    if (tid < 40) {
        const float invN = 1.f / (float)NNODES;
        int c = tid % 20;
        const float* st = (tid < 20) ? statsX : statsY;
        const float* gg = (tid < 20) ? gX : gY;
        const float* bb = (tid < 20) ? betX : betY;
        float mu = st[c] * invN;
        float var = st[20 + c] * invN - mu * mu;
        sMu[tid] = mu;
        sScv[tid] = gg[c] * rsqrtf(var + EPS_BN);
        sBeta[tid] = bb[c];
    }
    __syncthreads();

    const int row = bi * 128 + (tid >> 1);
    const int cb = (tid & 1) * 40;
    if (row >= NNODES) return;

    float a[40];
    {
        const float4* pa = (const float4*)(preX + (size_t)row * 20);
        const float4* pb = (const float4*)(preY + (size_t)row * 20);
        float4 va[5], vb[5];
#pragma unroll
        for (int i = 0; i < 5; i++) va[i] = pa[i];
#pragma unroll
        for (int i = 0; i < 5; i++) vb[i] = pb[i];
#pragma unroll
        for (int i = 0; i < 5; i++) {
            a[4 * i]     = va[i].x; a[4 * i + 1] = va[i].y;
            a[4 * i + 2] = va[i].z; a[4 * i + 3] = va[i].w;
            a[20 + 4 * i] = vb[i].x; a[21 + 4 * i] = vb[i].y;
            a[22 + 4 * i] = vb[i].z; a[23 + 4 * i] = vb[i].w;
        }
    }
#pragma unroll
    for (int k = 0; k < 40; k++) {
        float v = (a[k] - sMu[k]) * sScv[k] + sBeta[k];
        a[k] = (v >= 0.f) ? v : LSLOPE * v;
    }

    unsigned long long acc[20];
#pragma unroll
    for (int c = 0; c < 20; c++) acc[c] = 0ull;
#pragma unroll 8
    for (int k = 0; k < 40; k++) {
        unsigned long long a2 = pack2(a[k], a[k]);
        const unsigned long long* wrow = (const unsigned long long*)(&sW[k][cb]);
#pragma unroll
        for (int c = 0; c < 20; c++) acc[c] = ffma2(a2, wrow[c], acc[c]);
    }

    float res[40];
#pragma unroll
    for (int c = 0; c < 20; c++) {
        res[2 * c]     = __uint_as_float((unsigned)(acc[c] & 0xffffffffull)) + sb[cb + 2 * c];
        res[2 * c + 1] = __uint_as_float((unsigned)(acc[c] >> 32)) + sb[cb + 2 * c + 1];
    }
    float* dst = out + (size_t)row * 80 + cb;
#pragma unroll
    for (int c = 0; c < 40; c += 4)
        *(float4*)(dst + c) = make_float4(res[c], res[c + 1], res[c + 2], res[c + 3]);
}

// ---------- CSR aggregation: channel-pair lanes, 2 edges per warp-step ------
__global__ void __launch_bounds__(256)
agg_csr3(const float* __restrict__ q0, int nb0, float* __restrict__ p0, float* __restrict__ s0,
         const float* __restrict__ q1, int nb1, float* __restrict__ p1, float* __restrict__ s1,
         const float* __restrict__ q2, int nb2, float* __restrict__ p2, float* __restrict__ s2) {
    const int set = blockIdx.x / GA_BLK;
    const int bi = blockIdx.x - set * GA_BLK;
    const float* qkv = (set == 0) ? q0 : ((set == 1) ? q1 : q2);
    float* pre = (set == 0) ? p0 : ((set == 1) ? p1 : p2);
    float* stats = (set == 0) ? s0 : ((set == 1) ? s1 : s2);
    const int nbase = (set == 0) ? nb0 : ((set == 1) ? nb1 : nb2);

    const int wid = threadIdx.x >> 5, lane = threadIdx.x & 31;
    const int n = bi * 8 + wid;
    const int half = lane >> 4;
    const int hl = lane & 15;
    const bool act = hl < 10;
    const int cp = hl;

    __shared__ float sst[2][8][20];
    for (int l = threadIdx.x; l < 320; l += 256) ((float*)sst)[l] = 0.f;
    __syncthreads();

    if (n < NNODES) {
        const int gi = nbase + n;
        const int off0 = g_off[gi], off1 = g_off[gi + 1];
        float2 q2v = make_float2(0.f, 0.f);
        if (act) {
            q2v = *(const float2*)(qkv + (size_t)n * 80 + 2 * cp);
            q2v.x *= 0.22360679774997896f;
            q2v.y *= 0.22360679774997896f;
        }
        const uint32_t kvf = 20 + 4 * cp;
        float accx = 0.f, accy = 0.f, denom = 0.f;
        int p = off0;
        for (; p + 4 <= off1; p += 4) {
            int sA = g_csr[p + half];
            int sB = g_csr[p + 2 + half];
            float4 kv0 = act ? *(const float4*)(qkv + (size_t)sA * 80 + kvf)
                             : make_float4(0.f, 0.f, 0.f, 0.f);
            float4 kv1 = act ? *(const float4*)(qkv + (size_t)sB * 80 + kvf)
                             : make_float4(0.f, 0.f, 0.f, 0.f);
            float d0 = q2v.x * kv0.x + q2v.y * kv0.z;
            float d1 = q2v.x * kv1.x + q2v.y * kv1.z;
#pragma unroll
            for (int o = 8; o; o >>= 1) {
                d0 += __shfl_xor_sync(~0u, d0, o);
                d1 += __shfl_xor_sync(~0u, d1, o);
            }
            float e0 = __expf(d0), e1 = __expf(d1);
            denom += e0 + e1;
            accx += e0 * kv0.y + e1 * kv1.y;
            accy += e0 * kv0.w + e1 * kv1.w;
        }
        for (; p < off1; p += 2) {
            bool ea = (p + half) < off1;
            int sA = ea ? g_csr[p + half] : 0;
            float4 kv0 = (act && ea) ? *(const float4*)(qkv + (size_t)sA * 80 + kvf)
                                     : make_float4(0.f, 0.f, 0.f, 0.f);
            float d0 = q2v.x * kv0.x + q2v.y * kv0.z;
#pragma unroll
            for (int o = 8; o; o >>= 1) d0 += __shfl_xor_sync(~0u, d0, o);
            float e0 = ea ? __expf(d0) : 0.f;
            denom += e0;
            accx += e0 * kv0.y;
            accy += e0 * kv0.w;
        }
        accx += __shfl_xor_sync(~0u, accx, 16);
        accy += __shfl_xor_sync(~0u, accy, 16);
        denom += __shfl_xor_sync(~0u, denom, 16);
        float inv = 1.f / fmaxf(denom, 1e-16f);
        if (act && half == 0) {
            float2 sk = *(const float2*)(qkv + (size_t)n * 80 + 60 + 2 * cp);
            float rx = accx * inv + sk.x;
            float ry = accy * inv + sk.y;
            *(float2*)(pre + (size_t)n * 20 + 2 * cp) = make_float2(rx, ry);
            sst[0][wid][2 * cp] = rx;
            sst[0][wid][2 * cp + 1] = ry;
            sst[1][wid][2 * cp] = rx * rx;
            sst[1][wid][2 * cp + 1] = ry * ry;
        }
    }
    __syncthreads();
    if (threadIdx.x < 40) {
        int which = threadIdx.x / 20, cc = threadIdx.x % 20;
        float t = 0.f;
#pragma unroll
        for (int w = 0; w < 8; w++) t += sst[which][w][cc];
        atomicAdd(&stats[which * 20 + cc], t);
    }
}

// ------------------------- standalone bn_fc (last layer) + final FC --------
__global__ void __launch_bounds__(256)
bn_fc(const float* __restrict__ pre, const float* __restrict__ stats,
      const float* __restrict__ gamma, const float* __restrict__ beta,
      float* __restrict__ dst, int off) {
    int idx = blockIdx.x * blockDim.x + threadIdx.x;
    if (idx >= NNODES * 20) return;
    int n = idx / 20, c = idx % 20;
    const float invN = 1.f / (float)NNODES;
    float mu = stats[c] * invN;
    float var = stats[20 + c] * invN - mu * mu;
    float scv = gamma[c] * rsqrtf(var + EPS_BN);
    float v = (pre[idx] - mu) * scv + beta[c];
    v = (v >= 0.f) ? v : LSLOPE * v;
    dst[(size_t)n * 100 + off + c] = v;
}

__global__ void __launch_bounds__(128)
fc_kernel(const float* __restrict__ W, const float* __restrict__ b,
          float* __restrict__ out) {
    __shared__ float sw[200];
    for (int l = threadIdx.x; l < 200; l += blockDim.x) sw[l] = W[l];
    __syncthreads();
    int n = blockIdx.x * blockDim.x + threadIdx.x;
    if (n >= NNODES) return;
    float a0 = b[0], a1 = b[1];
    const float4* fp = (const float4*)(g_fc + (size_t)n * 100);
#pragma unroll
    for (int i = 0; i < 25; i++) {
        float4 f = fp[i];
        int c = 4 * i;
        a0 += f.x * sw[2 * c] + f.y * sw[2 * c + 2] + f.z * sw[2 * c + 4] + f.w * sw[2 * c + 6];
        a1 += f.x * sw[2 * c + 1] + f.y * sw[2 * c + 3] + f.z * sw[2 * c + 5] + f.w * sw[2 * c + 7];
    }
    out[2 * n] = a0;
    out[2 * n + 1] = a1;
}

// ------------------------- host orchestration -------------------------
extern "C" void kernel_launch(void* const* d_in, const int* in_sizes, int n_in,
                              void* d_out, int out_size) {
    (void)in_sizes; (void)n_in; (void)out_size;
    const float* features = (const float*)d_in[0];
    const int* edge_index = (const int*)d_in[3];
    const int* same2      = (const int*)d_in[4];
    const int* diff2      = (const int*)d_in[5];
    const float* c1_W0 = (const float*)d_in[6];
    const float* c1_b0 = (const float*)d_in[7];
    const float* c2_W0 = (const float*)d_in[8];
    const float* c2_b0 = (const float*)d_in[9];
    const float* c1_W  = (const float*)d_in[10];
    const float* c1_b  = (const float*)d_in[11];
    const float* c2_W  = (const float*)d_in[12];
    const float* c2_b  = (const float*)d_in[13];
    const float* c3_W  = (const float*)d_in[14];
    const float* c3_b  = (const float*)d_in[15];
    const float* bn1_g = (const float*)d_in[16];
    const float* bn1_b = (const float*)d_in[17];
    const float* bn2_g = (const float*)d_in[18];
    const float* bn2_b = (const float*)d_in[19];
    const float* bn3_g = (const float*)d_in[20];
    const float* bn3_b = (const float*)d_in[21];
    const float* fc_W  = (const float*)d_in[22];
    const float* fc_b  = (const float*)d_in[23];
    float* out = (float*)d_out;

    float *qkvA, *qkvB, *qkvC, *preA, *preB, *preC, *fcb, *stats;
    cudaGetSymbolAddress((void**)&qkvA, g_qkvA);
    cudaGetSymbolAddress((void**)&qkvB, g_qkvB);
    cudaGetSymbolAddress((void**)&qkvC, g_qkvC);
    cudaGetSymbolAddress((void**)&preA, g_preA);
    cudaGetSymbolAddress((void**)&preB, g_preB);
    cudaGetSymbolAddress((void**)&preC, g_preC);
    cudaGetSymbolAddress((void**)&fcb, g_fc);
    cudaGetSymbolAddress((void**)&stats, g_stats);

    const int G3E = (3 * NEDGE + 255) / 256;
    const int SMEM_MMA = (128 * SA_STRIDE + 160 * SB_STRIDE) * 2;

    cudaFuncSetAttribute(gemm_big_mma, cudaFuncAttributeMaxDynamicSharedMemorySize,
                         SMEM_MMA);

    // lazily-created side stream + events (resources only; identical work per call)
    static cudaStream_t s2 = nullptr;
    static cudaEvent_t evFork = nullptr, evJoin = nullptr;
    if (!s2) {
        cudaStreamCreateWithFlags(&s2, cudaStreamNonBlocking);
        cudaEventCreateWithFlags(&evFork, cudaEventDisableTiming);
        cudaEventCreateWithFlags(&evJoin, cudaEventDisableTiming);
    }

    // ---- fork: CSR build on s2, conv_w + big GEMM on default ----
    cudaEventRecord(evFork, 0);
    cudaStreamWaitEvent(s2, evFork, 0);

    zero_all<<<(NN3 + 255) / 256, 256, 0, s2>>>();
    hist_kernel<<<G3E, 256, 0, s2>>>(same2, diff2, edge_index);
    scanA<<<SCAN_BLOCKS, 1024, 0, s2>>>();
    scanB<<<1, 256, 0, s2>>>();
    scanC<<<SCAN_BLOCKS, 1024, 0, s2>>>();
    scatter_kernel<<<G3E, 256, 0, s2>>>(same2, diff2, edge_index);
    cudaEventRecord(evJoin, s2);

    conv_w<<<(2000 * 160 + 255) / 256, 256>>>(c1_W0, c2_W0);
    gemm_big_mma<<<GB_SM, 256, SMEM_MMA>>>(features, c1_b0, c2_b0, qkvA, qkvB);

    cudaStreamWaitEvent(0, evJoin, 0);  // join before first agg

    // ---- layer 0 ----
    agg_csr3<<<2 * GA_BLK, 256>>>(qkvA, 0, preA, stats + 0 * 40,
                                  qkvB, NNODES, preB, stats + 1 * 40,
                                  qkvA, 0, preA, stats + 0 * 40);

    for (int L = 0; L <= 4; L++) {
        const float* stX = stats + (3 * L) * 40;
        const float* stY = stats + (3 * L + 1) * 40;
        const float* g1 = bn1_g + L * 20; const float* b1 = bn1_b + L * 20;
        const float* g2 = bn2_g + L * 20; const float* b2 = bn2_b + L * 20;
        const int nsets = (L < 4) ? 3 : 1;
        const int bnBlocks = (L > 0) ? GN_BLK : 0;

        gemm_small3<<<nsets * GB_SM + bnBlocks, 256>>>(
            preA, preB, stX, stY, g1, b1, g2, b2,
            c3_W + (size_t)L * 3200, c3_b + (size_t)L * 80, qkvC,
            c1_W + (size_t)L * 3200, c1_b + (size_t)L * 80, qkvA,
            c2_W + (size_t)L * 3200, c2_b + (size_t)L * 80, qkvB,
            nsets,
            preC, stats + (3 * (L - 1) + 2) * 40,
            bn3_g + (L - 1) * 20, bn3_b + (L - 1) * 20, fcb, (L - 1) * 20);

        if (L < 4) {
            agg_csr3<<<3 * GA_BLK, 256>>>(qkvC, 2 * NNODES, preC, stats + (3 * L + 2) * 40,
                                          qkvA, 0, preA, stats + (3 * L + 3) * 40,
                                          qkvB, NNODES, preB, stats + (3 * L + 4) * 40);
        } else {
            agg_csr3<<<GA_BLK, 256>>>(qkvC, 2 * NNODES, preC, stats + (3 * L + 2) * 40,
                                      qkvC, 2 * NNODES, preC, stats + (3 * L + 2) * 40,
                                      qkvC, 2 * NNODES, preC, stats + (3 * L + 2) * 40);
        }
    }
    bn_fc<<<GN_BLK, 256>>>(preC, stats + 14 * 40, bn3_g + 80, bn3_b + 80, fcb, 80);

    fc_kernel<<<(NNODES + 127) / 128, 128>>>(fc_W, fc_b, out);
}

// round 13
// speedup vs baseline: 1.5355x; 1.5355x over previous
#include <cuda_runtime.h>
#include <cuda_bf16.h>
#include <cstdint>

#define NNODES 50000
#define NEDGE  1000000
#define DIN0   2000
#define EPS_BN 1e-5f
#define LSLOPE 0.01f
#define NN3    150000
#define SCAN_BLOCKS 147
#define GA_BLK 6250   /* (NNODES+7)/8 */
#define GB_SM  391    /* (NNODES+127)/128 */
#define GN_BLK 3907   /* (NNODES*20+255)/256 */

// qkv row layout (80 floats): [ q(0..19) | k0 v0 k1 v1 .. k19 v19 (20..59) | skip(60..79) ]

// ------------------------- scratch (device globals, zero-init) -------------
__device__ float g_qkvA[NNODES * 80];
__device__ float g_qkvB[NNODES * 80];
__device__ float g_qkvC[NNODES * 80];
__device__ float g_preA[NNODES * 20];
__device__ float g_preB[NNODES * 20];
__device__ float g_preC[NNODES * 20];
__device__ float g_fc[NNODES * 100];
__device__ float g_stats[15 * 40];
__device__ __nv_bfloat16 g_wt_hi[2000 * 160];
__device__ __nv_bfloat16 g_wt_lo[2000 * 160];
// CSR scratch
__device__ int g_cnt[NN3];
__device__ int g_off[NN3 + 1];
__device__ int g_cur[NN3];
__device__ int g_csr[3 * NEDGE];
__device__ int g_partraw[SCAN_BLOCKS];
__device__ int g_part[SCAN_BLOCKS];

// ------------------------- helpers -------------------------
__device__ __forceinline__ unsigned long long ffma2(unsigned long long a,
                                                    unsigned long long b,
                                                    unsigned long long c) {
    unsigned long long d;
    asm("fma.rn.f32x2 %0, %1, %2, %3;" : "=l"(d) : "l"(a), "l"(b), "l"(c));
    return d;
}
__device__ __forceinline__ unsigned long long pack2(float lo, float hi) {
    unsigned long long r;
    asm("mov.b64 %0, {%1, %2};" : "=l"(r) : "f"(lo), "f"(hi));
    return r;
}
__device__ __forceinline__ uint32_t smem_u32(const void* p) {
    uint32_t a;
    asm("{ .reg .u64 t; cvta.to.shared.u64 t, %1; cvt.u32.u64 %0, t; }"
        : "=r"(a) : "l"(p));
    return a;
}
__device__ __forceinline__ uint32_t packbf2(float a, float b, float* lo_a, float* lo_b) {
    __nv_bfloat16 ha = __float2bfloat16(a), hb = __float2bfloat16(b);
    *lo_a = a - __bfloat162float(ha);
    *lo_b = b - __bfloat162float(hb);
    __nv_bfloat162 p; p.x = ha; p.y = hb;
    return *(uint32_t*)&p;
}
__device__ __forceinline__ uint32_t packbf2s(float a, float b) {
    __nv_bfloat162 p; p.x = __float2bfloat16(a); p.y = __float2bfloat16(b);
    return *(uint32_t*)&p;
}
// logical qkv column (0..79) -> interleaved position
__device__ __forceinline__ int qkvpos(int c) {
    if (c < 20) return c;
    if (c < 40) return 2 * c - 20;   // k_c -> 20+2c
    if (c < 60) return 2 * c - 59;   // v_c -> 21+2c
    return c;
}

// ------------------------- CSR build -------------------------
__global__ void zero_all() {
    int i = blockIdx.x * blockDim.x + threadIdx.x;
    if (i < NN3) g_cnt[i] = 0;
    if (i < 15 * 40) g_stats[i] = 0.f;
}
__global__ void hist_kernel(const int* __restrict__ e0, const int* __restrict__ e1,
                            const int* __restrict__ e2) {
    int i = blockIdx.x * blockDim.x + threadIdx.x;
    if (i >= 3 * NEDGE) return;
    int set = i / NEDGE, e = i - set * NEDGE;
    const int* ei = (set == 0) ? e0 : ((set == 1) ? e1 : e2);
    atomicAdd(&g_cnt[set * NNODES + ei[NEDGE + e]], 1);
}
__global__ void __launch_bounds__(1024) scanA() {
    int gid = blockIdx.x * 1024 + threadIdx.x;
    int v = (gid < NN3) ? g_cnt[gid] : 0;
#pragma unroll
    for (int o = 16; o; o >>= 1) v += __shfl_xor_sync(~0u, v, o);
    __shared__ int sw[32];
    if ((threadIdx.x & 31) == 0) sw[threadIdx.x >> 5] = v;
    __syncthreads();
    if (threadIdx.x < 32) {
        int t = sw[threadIdx.x];
#pragma unroll
        for (int o = 16; o; o >>= 1) t += __shfl_xor_sync(~0u, t, o);
        if (threadIdx.x == 0) g_partraw[blockIdx.x] = t;
    }
}
__global__ void scanB() {
    __shared__ int sp[SCAN_BLOCKS + 1];
    int tid = threadIdx.x;
    if (tid < SCAN_BLOCKS) sp[tid + 1] = g_partraw[tid];
    if (tid == 0) sp[0] = 0;
    __syncthreads();
    if (tid == 0)
        for (int b = 1; b <= SCAN_BLOCKS; b++) sp[b] += sp[b - 1];
    __syncthreads();
    if (tid < SCAN_BLOCKS) g_part[tid] = sp[tid];
}
__global__ void __launch_bounds__(1024) scanC() {
    __shared__ int sdat[1024];
    int tid = threadIdx.x;
    int gid = blockIdx.x * 1024 + tid;
    int v = (gid < NN3) ? g_cnt[gid] : 0;
    sdat[tid] = v;
    __syncthreads();
    for (int o = 1; o < 1024; o <<= 1) {
        int t = (tid >= o) ? sdat[tid - o] : 0;
        __syncthreads();
        sdat[tid] += t;
        __syncthreads();
    }
    int excl = sdat[tid] - v + g_part[blockIdx.x];
    if (gid < NN3) { g_off[gid] = excl; g_cur[gid] = excl; }
    if (gid == 0) g_off[NN3] = 3 * NEDGE;
}
__global__ void scatter_kernel(const int* __restrict__ e0, const int* __restrict__ e1,
                               const int* __restrict__ e2) {
    int i = blockIdx.x * blockDim.x + threadIdx.x;
    if (i >= 3 * NEDGE) return;
    int set = i / NEDGE, e = i - set * NEDGE;
    const int* ei = (set == 0) ? e0 : ((set == 1) ? e1 : e2);
    int s = ei[e], d = ei[NEDGE + e];
    int pos = atomicAdd(&g_cur[set * NNODES + d], 1);
    g_csr[pos] = s;
}

// ------------- W split+transpose with kv-interleave column permutation -----
__global__ void conv_w(const float* __restrict__ W1, const float* __restrict__ W2) {
    int idx = blockIdx.x * blockDim.x + threadIdx.x;
    if (idx >= 2000 * 160) return;
    int k = idx / 160, n = idx - k * 160;
    const float* Wsrc = (n < 80) ? W1 : W2;
    int nn = (n < 80) ? n : n - 80;
    int s = nn / 20, o = nn % 20;
    float w = Wsrc[((size_t)s * 2000 + k) * 20 + o];
    __nv_bfloat16 h = __float2bfloat16(w);
    int nperm = ((n < 80) ? 0 : 80) + qkvpos(nn);
    g_wt_hi[(size_t)k * 160 + nperm] = h;
    g_wt_lo[(size_t)k * 160 + nperm] = __float2bfloat16(w - __bfloat162float(h));
}

// ------------------------- big GEMM via mma.sync bf16-split ----------------
#define SA_STRIDE 168
#define SB_STRIDE 168

__global__ void __launch_bounds__(256)
gemm_big_mma(const float* __restrict__ A,
             const float* __restrict__ b1, const float* __restrict__ b2,
             float* __restrict__ outA, float* __restrict__ outB) {
    extern __shared__ __align__(16) char dsm[];
    __nv_bfloat16* sA = (__nv_bfloat16*)dsm;
    __nv_bfloat16* sB = (__nv_bfloat16*)(dsm + 128 * SA_STRIDE * 2);
    __shared__ float s_bias[160];

    const int tid = threadIdx.x, wid = tid >> 5, lane = tid & 31;
    const int rowbase = blockIdx.x * 128;
    if (tid < 160) {
        int g = tid / 80, c = tid % 80;
        float bv = (g == 0) ? b1[c] : b2[c];
        s_bias[g * 80 + qkvpos(c)] = bv;
    }

    float acc[20][4];
#pragma unroll
    for (int t = 0; t < 20; t++)
#pragma unroll
        for (int i = 0; i < 4; i++) acc[t][i] = 0.f;

    const int r_in = lane & 7, blkb = (lane >> 3) & 1, kh = (lane >> 4) & 1;
    const uint32_t aBase =
        smem_u32(sA) + (uint32_t)((wid * 16 + blkb * 8 + r_in) * SA_STRIDE + kh * 8) * 2;
    const uint32_t bBase2 = smem_u32(sB) + (uint32_t)((lane & 15) * SB_STRIDE) * 2;
    const uint32_t bBase4 = smem_u32(sB) + (uint32_t)(lane * SB_STRIDE) * 2;

    const int a0off[7] = {0, 32, 64, 16, 48, 80, 112};
    const int a1off[7] = {16, 48, 0, 32, 64, 96, 128};
    const int browt[7] = {0, 32, 64, 96, 128, 0, 32};

    for (int ch = 0; ch < 25; ch++) {
        const int k0 = ch * 80;
#pragma unroll
        for (int it = 0; it < 13; it++) {
            int q = tid + it * 256;
            if (q < 3200) {
                int row = q / 20, c16 = q - row * 20;
                int kk = (row >= 80) ? row - 80 : row;
                const __nv_bfloat16* src =
                    ((row >= 80) ? g_wt_lo : g_wt_hi) + (size_t)(k0 + kk) * 160 + c16 * 8;
                uint32_t dst = smem_u32(sB) + (uint32_t)(row * SB_STRIDE + c16 * 8) * 2;
                asm volatile("cp.async.ca.shared.global [%0], [%1], 16;"
                             :: "r"(dst), "l"(src));
            }
        }
        asm volatile("cp.async.commit_group;" ::: "memory");
#pragma unroll
        for (int it = 0; it < 10; it++) {
            int q = tid + it * 256;
            int r = q / 20, f = q - r * 20;
            int row = rowbase + r;
            float4 v = (row < NNODES)
                           ? *(const float4*)(A + (size_t)row * 2000 + k0 + f * 4)
                           : make_float4(0.f, 0.f, 0.f, 0.f);
            float l0, l1, l2, l3;
            uint32_t h0 = packbf2(v.x, v.y, &l0, &l1);
            uint32_t h1 = packbf2(v.z, v.w, &l2, &l3);
            uint32_t p0 = packbf2s(l0, l1), p1 = packbf2s(l2, l3);
            int k = f * 4;
            __nv_bfloat16* rp = sA + r * SA_STRIDE;
            *(uint32_t*)(rp + k) = h0;
            *(uint32_t*)(rp + k + 2) = h1;
            *(uint32_t*)(rp + 80 + k) = p0;
            *(uint32_t*)(rp + 82 + k) = p1;
        }
        asm volatile("cp.async.wait_group 0;" ::: "memory");
        __syncthreads();
#pragma unroll
        for (int jp = 0; jp < 7; jp++) {
            uint32_t a0, a1, a2, a3, c0, c1, c2, c3;
            asm volatile(
                "ldmatrix.sync.aligned.m8n8.x4.shared.b16 {%0,%1,%2,%3}, [%4];"
                : "=r"(a0), "=r"(a1), "=r"(a2), "=r"(a3)
                : "r"(aBase + (uint32_t)a0off[jp] * 2));
            asm volatile(
                "ldmatrix.sync.aligned.m8n8.x4.shared.b16 {%0,%1,%2,%3}, [%4];"
                : "=r"(c0), "=r"(c1), "=r"(c2), "=r"(c3)
                : "r"(aBase + (uint32_t)a1off[jp] * 2));
            const uint32_t bb = bBase4 + (uint32_t)(browt[jp] * SB_STRIDE) * 2;
#pragma unroll
            for (int t = 0; t < 20; t++) {
                uint32_t b0, b1, b2, b3;
                asm volatile(
                    "ldmatrix.sync.aligned.m8n8.x4.trans.shared.b16 {%0,%1,%2,%3}, [%4];"
                    : "=r"(b0), "=r"(b1), "=r"(b2), "=r"(b3)
                    : "r"(bb + (uint32_t)t * 16));
                asm volatile(
                    "mma.sync.aligned.m16n8k16.row.col.f32.bf16.bf16.f32 "
                    "{%0,%1,%2,%3}, {%4,%5,%6,%7}, {%8,%9}, {%0,%1,%2,%3};"
                    : "+f"(acc[t][0]), "+f"(acc[t][1]), "+f"(acc[t][2]), "+f"(acc[t][3])
                    : "r"(a0), "r"(a1), "r"(a2), "r"(a3), "r"(b0), "r"(b1));
                asm volatile(
                    "mma.sync.aligned.m16n8k16.row.col.f32.bf16.bf16.f32 "
                    "{%0,%1,%2,%3}, {%4,%5,%6,%7}, {%8,%9}, {%0,%1,%2,%3};"
                    : "+f"(acc[t][0]), "+f"(acc[t][1]), "+f"(acc[t][2]), "+f"(acc[t][3])
                    : "r"(c0), "r"(c1), "r"(c2), "r"(c3), "r"(b2), "r"(b3));
            }
        }
        {
            uint32_t a0, a1, a2, a3;
            asm volatile(
                "ldmatrix.sync.aligned.m8n8.x4.shared.b16 {%0,%1,%2,%3}, [%4];"
                : "=r"(a0), "=r"(a1), "=r"(a2), "=r"(a3)
                : "r"(aBase + 144u * 2));
            const uint32_t bb = bBase2 + (uint32_t)(64 * SB_STRIDE) * 2;
#pragma unroll
            for (int t = 0; t < 20; t++) {
                uint32_t b0, b1;
                asm volatile(
                    "ldmatrix.sync.aligned.m8n8.x2.trans.shared.b16 {%0,%1}, [%2];"
                    : "=r"(b0), "=r"(b1)
                    : "r"(bb + (uint32_t)t * 16));
                asm volatile(
                    "mma.sync.aligned.m16n8k16.row.col.f32.bf16.bf16.f32 "
                    "{%0,%1,%2,%3}, {%4,%5,%6,%7}, {%8,%9}, {%0,%1,%2,%3};"
                    : "+f"(acc[t][0]), "+f"(acc[t][1]), "+f"(acc[t][2]), "+f"(acc[t][3])
                    : "r"(a0), "r"(a1), "r"(a2), "r"(a3), "r"(b0), "r"(b1));
            }
        }
        __syncthreads();
    }

    const int r0 = rowbase + wid * 16 + lane / 4;
    const int r1 = r0 + 8;
    const int cb = (lane & 3) * 2;
#pragma unroll
    for (int t = 0; t < 20; t++) {
        int col = t * 8 + cb;
        float* base = (col < 80) ? outA : outB;
        int cc = (col < 80) ? col : col - 80;
        float bia0 = s_bias[col], bia1 = s_bias[col + 1];
        if (r0 < NNODES)
            *(float2*)(base + (size_t)r0 * 80 + cc) =
                make_float2(acc[t][0] + bia0, acc[t][1] + bia1);
        if (r1 < NNODES)
            *(float2*)(base + (size_t)r1 * 80 + cc) =
                make_float2(acc[t][2] + bia0, acc[t][3] + bia1);
    }
}

// --------------- fused small GEMMs (+ optional bn_fc block range) ----------
__global__ void __launch_bounds__(256)
gemm_small3(const float* __restrict__ preA, const float* __restrict__ preB,
            const float* __restrict__ stX, const float* __restrict__ stY,
            const float* __restrict__ g1, const float* __restrict__ be1,
            const float* __restrict__ g2, const float* __restrict__ be2,
            const float* __restrict__ Wc3, const float* __restrict__ bc3,
            float* __restrict__ outC,
            const float* __restrict__ Wc1, const float* __restrict__ bc1,
            float* __restrict__ outA,
            const float* __restrict__ Wc2, const float* __restrict__ bc2,
            float* __restrict__ outB,
            int nsets,
            const float* __restrict__ bnPre, const float* __restrict__ bnStats,
            const float* __restrict__ bnG, const float* __restrict__ bnB,
            float* __restrict__ bnDst, int bnOff) {
    const int bnStart = nsets * GB_SM;
    if ((int)blockIdx.x >= bnStart) {
        int idx = (blockIdx.x - bnStart) * 256 + threadIdx.x;
        if (idx >= NNODES * 20) return;
        int n = idx / 20, c = idx % 20;
        const float invN = 1.f / (float)NNODES;
        float mu = bnStats[c] * invN;
        float var = bnStats[20 + c] * invN - mu * mu;
        float scv = bnG[c] * rsqrtf(var + EPS_BN);
        float v = (bnPre[idx] - mu) * scv + bnB[c];
        v = (v >= 0.f) ? v : LSLOPE * v;
        bnDst[(size_t)n * 100 + bnOff + c] = v;
        return;
    }
    const int set = blockIdx.x / GB_SM;
    const int bi = blockIdx.x - set * GB_SM;
    const bool swap = (set == 2);
    const float* preX = swap ? preB : preA;
    const float* preY = swap ? preA : preB;
    const float* statsX = swap ? stY : stX;
    const float* statsY = swap ? stX : stY;
    const float* gX = swap ? g2 : g1;
    const float* betX = swap ? be2 : be1;
    const float* gY = swap ? g1 : g2;
    const float* betY = swap ? be1 : be2;
    const float* W = (set == 0) ? Wc3 : ((set == 1) ? Wc1 : Wc2);
    const float* b = (set == 0) ? bc3 : ((set == 1) ? bc1 : bc2);
    float* out = (set == 0) ? outC : ((set == 1) ? outA : outB);

    __shared__ __align__(8) float sW[40][80];
    __shared__ float sb[80];
    __shared__ float sMu[40], sScv[40], sBeta[40];
    const int tid = threadIdx.x;
    for (int l = tid; l < 3200; l += 256) {
        int s = l / 800, rem = l % 800, k = rem / 20, o = rem % 20;
        sW[k][qkvpos(s * 20 + o)] = W[l];
    }
    if (tid < 80) sb[qkvpos(tid)] = b[tid];
    if (tid < 40) {
        const float invN = 1.f / (float)NNODES;
        int c = tid % 20;
        const float* st = (tid < 20) ? statsX : statsY;
        const float* gg = (tid < 20) ? gX : gY;
        const float* bb = (tid < 20) ? betX : betY;
        float mu = st[c] * invN;
        float var = st[20 + c] * invN - mu * mu;
        sMu[tid] = mu;
        sScv[tid] = gg[c] * rsqrtf(var + EPS_BN);
        sBeta[tid] = bb[c];
    }
    __syncthreads();

    const int row = bi * 128 + (tid >> 1);
    const int cb = (tid & 1) * 40;
    if (row >= NNODES) return;

    float a[40];
    {
        const float4* pa = (const float4*)(preX + (size_t)row * 20);
        const float4* pb = (const float4*)(preY + (size_t)row * 20);
        float4 va[5], vb[5];
#pragma unroll
        for (int i = 0; i < 5; i++) va[i] = pa[i];
#pragma unroll
        for (int i = 0; i < 5; i++) vb[i] = pb[i];
#pragma unroll
        for (int i = 0; i < 5; i++) {
            a[4 * i]     = va[i].x; a[4 * i + 1] = va[i].y;
            a[4 * i + 2] = va[i].z; a[4 * i + 3] = va[i].w;
            a[20 + 4 * i] = vb[i].x; a[21 + 4 * i] = vb[i].y;
            a[22 + 4 * i] = vb[i].z; a[23 + 4 * i] = vb[i].w;
        }
    }
#pragma unroll
    for (int k = 0; k < 40; k++) {
        float v = (a[k] - sMu[k]) * sScv[k] + sBeta[k];
        a[k] = (v >= 0.f) ? v : LSLOPE * v;
    }

    unsigned long long acc[20];
#pragma unroll
    for (int c = 0; c < 20; c++) acc[c] = 0ull;
#pragma unroll 8
    for (int k = 0; k < 40; k++) {
        unsigned long long a2 = pack2(a[k], a[k]);
        const unsigned long long* wrow = (const unsigned long long*)(&sW[k][cb]);
#pragma unroll
        for (int c = 0; c < 20; c++) acc[c] = ffma2(a2, wrow[c], acc[c]);
    }

    float res[40];
#pragma unroll
    for (int c = 0; c < 20; c++) {
        res[2 * c]     = __uint_as_float((unsigned)(acc[c] & 0xffffffffull)) + sb[cb + 2 * c];
        res[2 * c + 1] = __uint_as_float((unsigned)(acc[c] >> 32)) + sb[cb + 2 * c + 1];
    }
    float* dst = out + (size_t)row * 80 + cb;
#pragma unroll
    for (int c = 0; c < 40; c += 4)
        *(float4*)(dst + c) = make_float4(res[c], res[c + 1], res[c + 2], res[c + 3]);
}

// ---------- CSR aggregation: channel-pair lanes, 2 edges per warp-step ------
__global__ void __launch_bounds__(256)
agg_csr3(const float* __restrict__ q0, int nb0, float* __restrict__ p0, float* __restrict__ s0,
         const float* __restrict__ q1, int nb1, float* __restrict__ p1, float* __restrict__ s1,
         const float* __restrict__ q2, int nb2, float* __restrict__ p2, float* __restrict__ s2) {
    const int set = blockIdx.x / GA_BLK;
    const int bi = blockIdx.x - set * GA_BLK;
    const float* qkv = (set == 0) ? q0 : ((set == 1) ? q1 : q2);
    float* pre = (set == 0) ? p0 : ((set == 1) ? p1 : p2);
    float* stats = (set == 0) ? s0 : ((set == 1) ? s1 : s2);
    const int nbase = (set == 0) ? nb0 : ((set == 1) ? nb1 : nb2);

    const int wid = threadIdx.x >> 5, lane = threadIdx.x & 31;
    const int n = bi * 8 + wid;
    const int half = lane >> 4;
    const int hl = lane & 15;
    const bool act = hl < 10;
    const int cp = hl;

    __shared__ float sst[2][8][20];
    for (int l = threadIdx.x; l < 320; l += 256) ((float*)sst)[l] = 0.f;
    __syncthreads();

    if (n < NNODES) {
        const int gi = nbase + n;
        const int off0 = g_off[gi], off1 = g_off[gi + 1];
        float2 q2v = make_float2(0.f, 0.f);
        if (act) {
            q2v = *(const float2*)(qkv + (size_t)n * 80 + 2 * cp);
            q2v.x *= 0.22360679774997896f;
            q2v.y *= 0.22360679774997896f;
        }
        const uint32_t kvf = 20 + 4 * cp;
        float accx = 0.f, accy = 0.f, denom = 0.f;
        int p = off0;
        for (; p + 4 <= off1; p += 4) {
            int sA = g_csr[p + half];
            int sB = g_csr[p + 2 + half];
            float4 kv0 = act ? *(const float4*)(qkv + (size_t)sA * 80 + kvf)
                             : make_float4(0.f, 0.f, 0.f, 0.f);
            float4 kv1 = act ? *(const float4*)(qkv + (size_t)sB * 80 + kvf)
                             : make_float4(0.f, 0.f, 0.f, 0.f);
            float d0 = q2v.x * kv0.x + q2v.y * kv0.z;
            float d1 = q2v.x * kv1.x + q2v.y * kv1.z;
#pragma unroll
            for (int o = 8; o; o >>= 1) {
                d0 += __shfl_xor_sync(~0u, d0, o);
                d1 += __shfl_xor_sync(~0u, d1, o);
            }
            float e0 = __expf(d0), e1 = __expf(d1);
            denom += e0 + e1;
            accx += e0 * kv0.y + e1 * kv1.y;
            accy += e0 * kv0.w + e1 * kv1.w;
        }
        for (; p < off1; p += 2) {
            bool ea = (p + half) < off1;
            int sA = ea ? g_csr[p + half] : 0;
            float4 kv0 = (act && ea) ? *(const float4*)(qkv + (size_t)sA * 80 + kvf)
                                     : make_float4(0.f, 0.f, 0.f, 0.f);
            float d0 = q2v.x * kv0.x + q2v.y * kv0.z;
#pragma unroll
            for (int o = 8; o; o >>= 1) d0 += __shfl_xor_sync(~0u, d0, o);
            float e0 = ea ? __expf(d0) : 0.f;
            denom += e0;
            accx += e0 * kv0.y;
            accy += e0 * kv0.w;
        }
        accx += __shfl_xor_sync(~0u, accx, 16);
        accy += __shfl_xor_sync(~0u, accy, 16);
        denom += __shfl_xor_sync(~0u, denom, 16);
        float inv = 1.f / fmaxf(denom, 1e-16f);
        if (act && half == 0) {
            float2 sk = *(const float2*)(qkv + (size_t)n * 80 + 60 + 2 * cp);
            float rx = accx * inv + sk.x;
            float ry = accy * inv + sk.y;
            *(float2*)(pre + (size_t)n * 20 + 2 * cp) = make_float2(rx, ry);
            sst[0][wid][2 * cp] = rx;
            sst[0][wid][2 * cp + 1] = ry;
            sst[1][wid][2 * cp] = rx * rx;
            sst[1][wid][2 * cp + 1] = ry * ry;
        }
    }
    __syncthreads();
    if (threadIdx.x < 40) {
        int which = threadIdx.x / 20, cc = threadIdx.x % 20;
        float t = 0.f;
#pragma unroll
        for (int w = 0; w < 8; w++) t += sst[which][w][cc];
        atomicAdd(&stats[which * 20 + cc], t);
    }
}

// ------------------------- standalone bn_fc (last layer) + final FC --------
__global__ void __launch_bounds__(256)
bn_fc(const float* __restrict__ pre, const float* __restrict__ stats,
      const float* __restrict__ gamma, const float* __restrict__ beta,
      float* __restrict__ dst, int off) {
    int idx = blockIdx.x * blockDim.x + threadIdx.x;
    if (idx >= NNODES * 20) return;
    int n = idx / 20, c = idx % 20;
    const float invN = 1.f / (float)NNODES;
    float mu = stats[c] * invN;
    float var = stats[20 + c] * invN - mu * mu;
    float scv = gamma[c] * rsqrtf(var + EPS_BN);
    float v = (pre[idx] - mu) * scv + beta[c];
    v = (v >= 0.f) ? v : LSLOPE * v;
    dst[(size_t)n * 100 + off + c] = v;
}

__global__ void __launch_bounds__(128)
fc_kernel(const float* __restrict__ W, const float* __restrict__ b,
          float* __restrict__ out) {
    __shared__ float sw[200];
    for (int l = threadIdx.x; l < 200; l += blockDim.x) sw[l] = W[l];
    __syncthreads();
    int n = blockIdx.x * blockDim.x + threadIdx.x;
    if (n >= NNODES) return;
    float a0 = b[0], a1 = b[1];
    const float4* fp = (const float4*)(g_fc + (size_t)n * 100);
#pragma unroll
    for (int i = 0; i < 25; i++) {
        float4 f = fp[i];
        int c = 4 * i;
        a0 += f.x * sw[2 * c] + f.y * sw[2 * c + 2] + f.z * sw[2 * c + 4] + f.w * sw[2 * c + 6];
        a1 += f.x * sw[2 * c + 1] + f.y * sw[2 * c + 3] + f.z * sw[2 * c + 5] + f.w * sw[2 * c + 7];
    }
    out[2 * n] = a0;
    out[2 * n + 1] = a1;
}

// ------------------------- host orchestration -------------------------
extern "C" void kernel_launch(void* const* d_in, const int* in_sizes, int n_in,
                              void* d_out, int out_size) {
    (void)in_sizes; (void)n_in; (void)out_size;
    const float* features = (const float*)d_in[0];
    const int* edge_index = (const int*)d_in[3];
    const int* same2      = (const int*)d_in[4];
    const int* diff2      = (const int*)d_in[5];
    const float* c1_W0 = (const float*)d_in[6];
    const float* c1_b0 = (const float*)d_in[7];
    const float* c2_W0 = (const float*)d_in[8];
    const float* c2_b0 = (const float*)d_in[9];
    const float* c1_W  = (const float*)d_in[10];
    const float* c1_b  = (const float*)d_in[11];
    const float* c2_W  = (const float*)d_in[12];
    const float* c2_b  = (const float*)d_in[13];
    const float* c3_W  = (const float*)d_in[14];
    const float* c3_b  = (const float*)d_in[15];
    const float* bn1_g = (const float*)d_in[16];
    const float* bn1_b = (const float*)d_in[17];
    const float* bn2_g = (const float*)d_in[18];
    const float* bn2_b = (const float*)d_in[19];
    const float* bn3_g = (const float*)d_in[20];
    const float* bn3_b = (const float*)d_in[21];
    const float* fc_W  = (const float*)d_in[22];
    const float* fc_b  = (const float*)d_in[23];
    float* out = (float*)d_out;

    float *qkvA, *qkvB, *qkvC, *preA, *preB, *preC, *fcb, *stats;
    cudaGetSymbolAddress((void**)&qkvA, g_qkvA);
    cudaGetSymbolAddress((void**)&qkvB, g_qkvB);
    cudaGetSymbolAddress((void**)&qkvC, g_qkvC);
    cudaGetSymbolAddress((void**)&preA, g_preA);
    cudaGetSymbolAddress((void**)&preB, g_preB);
    cudaGetSymbolAddress((void**)&preC, g_preC);
    cudaGetSymbolAddress((void**)&fcb, g_fc);
    cudaGetSymbolAddress((void**)&stats, g_stats);

    const int G3E = (3 * NEDGE + 255) / 256;
    const int SMEM_MMA = (128 * SA_STRIDE + 160 * SB_STRIDE) * 2;

    cudaFuncSetAttribute(gemm_big_mma, cudaFuncAttributeMaxDynamicSharedMemorySize,
                         SMEM_MMA);

    // lazily-created side stream + events (resources only; identical work per call)
    static cudaStream_t s2 = nullptr;
    static cudaEvent_t evFork = nullptr, evJoin = nullptr;
    if (!s2) {
        cudaStreamCreateWithFlags(&s2, cudaStreamNonBlocking);
        cudaEventCreateWithFlags(&evFork, cudaEventDisableTiming);
        cudaEventCreateWithFlags(&evJoin, cudaEventDisableTiming);
    }

    // ---- fork: CSR build on s2, conv_w + big GEMM on default ----
    cudaEventRecord(evFork, 0);
    cudaStreamWaitEvent(s2, evFork, 0);

    zero_all<<<(NN3 + 255) / 256, 256, 0, s2>>>();
    hist_kernel<<<G3E, 256, 0, s2>>>(same2, diff2, edge_index);
    scanA<<<SCAN_BLOCKS, 1024, 0, s2>>>();
    scanB<<<1, 256, 0, s2>>>();
    scanC<<<SCAN_BLOCKS, 1024, 0, s2>>>();
    scatter_kernel<<<G3E, 256, 0, s2>>>(same2, diff2, edge_index);
    cudaEventRecord(evJoin, s2);

    conv_w<<<(2000 * 160 + 255) / 256, 256>>>(c1_W0, c2_W0);
    gemm_big_mma<<<GB_SM, 256, SMEM_MMA>>>(features, c1_b0, c2_b0, qkvA, qkvB);

    cudaStreamWaitEvent(0, evJoin, 0);  // join before first agg

    // ---- layer 0 ----
    agg_csr3<<<2 * GA_BLK, 256>>>(qkvA, 0, preA, stats + 0 * 40,
                                  qkvB, NNODES, preB, stats + 1 * 40,
                                  qkvA, 0, preA, stats + 0 * 40);

    for (int L = 0; L <= 4; L++) {
        const float* stX = stats + (3 * L) * 40;
        const float* stY = stats + (3 * L + 1) * 40;
        const float* g1 = bn1_g + L * 20; const float* b1 = bn1_b + L * 20;
        const float* g2 = bn2_g + L * 20; const float* b2 = bn2_b + L * 20;
        const int nsets = (L < 4) ? 3 : 1;
        const int bnBlocks = (L > 0) ? GN_BLK : 0;

        gemm_small3<<<nsets * GB_SM + bnBlocks, 256>>>(
            preA, preB, stX, stY, g1, b1, g2, b2,
            c3_W + (size_t)L * 3200, c3_b + (size_t)L * 80, qkvC,
            c1_W + (size_t)L * 3200, c1_b + (size_t)L * 80, qkvA,
            c2_W + (size_t)L * 3200, c2_b + (size_t)L * 80, qkvB,
            nsets,
            preC, stats + (3 * (L - 1) + 2) * 40,
            bn3_g + (L - 1) * 20, bn3_b + (L - 1) * 20, fcb, (L - 1) * 20);

        if (L < 4) {
            agg_csr3<<<3 * GA_BLK, 256>>>(qkvC, 2 * NNODES, preC, stats + (3 * L + 2) * 40,
                                          qkvA, 0, preA, stats + (3 * L + 3) * 40,
                                          qkvB, NNODES, preB, stats + (3 * L + 4) * 40);
        } else {
            agg_csr3<<<GA_BLK, 256>>>(qkvC, 2 * NNODES, preC, stats + (3 * L + 2) * 40,
                                      qkvC, 2 * NNODES, preC, stats + (3 * L + 2) * 40,
                                      qkvC, 2 * NNODES, preC, stats + (3 * L + 2) * 40);
        }
    }
    bn_fc<<<GN_BLK, 256>>>(preC, stats + 14 * 40, bn3_g + 80, bn3_b + 80, fcb, 80);

    fc_kernel<<<(NNODES + 127) / 128, 128>>>(fc_W, fc_b, out);
}

// round 14
// speedup vs baseline: 1.5943x; 1.0383x over previous
#include <cuda_runtime.h>
#include <cuda_bf16.h>
#include <cstdint>

#define NNODES 50000
#define NEDGE  1000000
#define DIN0   2000
#define EPS_BN 1e-5f
#define LSLOPE 0.01f
#define NN3    150000
#define SCAN_BLOCKS 147
#define GA_BLK 6250   /* (NNODES+7)/8 */
#define GB_SM  391    /* (NNODES+127)/128 */
#define GN_BLK 3907   /* (NNODES*20+255)/256 */

// qkv row layout (80 floats): [ q(0..19) | k0 v0 k1 v1 .. k19 v19 (20..59) | skip(60..79) ]

// ------------------------- scratch (device globals, zero-init) -------------
__device__ float g_qkvA[NNODES * 80];
__device__ float g_qkvB[NNODES * 80];
__device__ float g_qkvC[NNODES * 80];
__device__ float g_preA[NNODES * 20];
__device__ float g_preB[NNODES * 20];
__device__ float g_preC[NNODES * 20];
__device__ float g_fc[NNODES * 100];
__device__ float g_stats[15 * 40];
__device__ __nv_bfloat16 g_wt_hi[2000 * 160];
__device__ __nv_bfloat16 g_wt_lo[2000 * 160];
// CSR scratch
__device__ int g_cnt[NN3];
__device__ int g_off[NN3 + 1];
__device__ int g_cur[NN3];
__device__ int g_csr[3 * NEDGE];
__device__ int g_partraw[SCAN_BLOCKS];
__device__ int g_part[SCAN_BLOCKS];

// ------------------------- helpers -------------------------
__device__ __forceinline__ unsigned long long ffma2(unsigned long long a,
                                                    unsigned long long b,
                                                    unsigned long long c) {
    unsigned long long d;
    asm("fma.rn.f32x2 %0, %1, %2, %3;" : "=l"(d) : "l"(a), "l"(b), "l"(c));
    return d;
}
__device__ __forceinline__ unsigned long long pack2(float lo, float hi) {
    unsigned long long r;
    asm("mov.b64 %0, {%1, %2};" : "=l"(r) : "f"(lo), "f"(hi));
    return r;
}
__device__ __forceinline__ uint32_t smem_u32(const void* p) {
    uint32_t a;
    asm("{ .reg .u64 t; cvta.to.shared.u64 t, %1; cvt.u32.u64 %0, t; }"
        : "=r"(a) : "l"(p));
    return a;
}
__device__ __forceinline__ uint32_t packbf2(float a, float b, float* lo_a, float* lo_b) {
    __nv_bfloat16 ha = __float2bfloat16(a), hb = __float2bfloat16(b);
    *lo_a = a - __bfloat162float(ha);
    *lo_b = b - __bfloat162float(hb);
    __nv_bfloat162 p; p.x = ha; p.y = hb;
    return *(uint32_t*)&p;
}
__device__ __forceinline__ uint32_t packbf2s(float a, float b) {
    __nv_bfloat162 p; p.x = __float2bfloat16(a); p.y = __float2bfloat16(b);
    return *(uint32_t*)&p;
}
// logical qkv column (0..79) -> interleaved position
__device__ __forceinline__ int qkvpos(int c) {
    if (c < 20) return c;
    if (c < 40) return 2 * c - 20;   // k_c -> 20+2c
    if (c < 60) return 2 * c - 59;   // v_c -> 21+2c
    return c;
}

// ------------------------- CSR build -------------------------
__global__ void zero_all() {
    int i = blockIdx.x * blockDim.x + threadIdx.x;
    if (i < NN3) g_cnt[i] = 0;
    if (i < 15 * 40) g_stats[i] = 0.f;
}
__global__ void hist_kernel(const int* __restrict__ e0, const int* __restrict__ e1,
                            const int* __restrict__ e2) {
    int i = blockIdx.x * blockDim.x + threadIdx.x;
    if (i >= 3 * NEDGE) return;
    int set = i / NEDGE, e = i - set * NEDGE;
    const int* ei = (set == 0) ? e0 : ((set == 1) ? e1 : e2);
    atomicAdd(&g_cnt[set * NNODES + ei[NEDGE + e]], 1);
}
__global__ void __launch_bounds__(1024) scanA() {
    int gid = blockIdx.x * 1024 + threadIdx.x;
    int v = (gid < NN3) ? g_cnt[gid] : 0;
#pragma unroll
    for (int o = 16; o; o >>= 1) v += __shfl_xor_sync(~0u, v, o);
    __shared__ int sw[32];
    if ((threadIdx.x & 31) == 0) sw[threadIdx.x >> 5] = v;
    __syncthreads();
    if (threadIdx.x < 32) {
        int t = sw[threadIdx.x];
#pragma unroll
        for (int o = 16; o; o >>= 1) t += __shfl_xor_sync(~0u, t, o);
        if (threadIdx.x == 0) g_partraw[blockIdx.x] = t;
    }
}
__global__ void scanB() {
    __shared__ int sp[SCAN_BLOCKS + 1];
    int tid = threadIdx.x;
    if (tid < SCAN_BLOCKS) sp[tid + 1] = g_partraw[tid];
    if (tid == 0) sp[0] = 0;
    __syncthreads();
    if (tid == 0)
        for (int b = 1; b <= SCAN_BLOCKS; b++) sp[b] += sp[b - 1];
    __syncthreads();
    if (tid < SCAN_BLOCKS) g_part[tid] = sp[tid];
}
__global__ void __launch_bounds__(1024) scanC() {
    __shared__ int sdat[1024];
    int tid = threadIdx.x;
    int gid = blockIdx.x * 1024 + tid;
    int v = (gid < NN3) ? g_cnt[gid] : 0;
    sdat[tid] = v;
    __syncthreads();
    for (int o = 1; o < 1024; o <<= 1) {
        int t = (tid >= o) ? sdat[tid - o] : 0;
        __syncthreads();
        sdat[tid] += t;
        __syncthreads();
    }
    int excl = sdat[tid] - v + g_part[blockIdx.x];
    if (gid < NN3) { g_off[gid] = excl; g_cur[gid] = excl; }
    if (gid == 0) g_off[NN3] = 3 * NEDGE;
}
__global__ void scatter_kernel(const int* __restrict__ e0, const int* __restrict__ e1,
                               const int* __restrict__ e2) {
    int i = blockIdx.x * blockDim.x + threadIdx.x;
    if (i >= 3 * NEDGE) return;
    int set = i / NEDGE, e = i - set * NEDGE;
    const int* ei = (set == 0) ? e0 : ((set == 1) ? e1 : e2);
    int s = ei[e], d = ei[NEDGE + e];
    int pos = atomicAdd(&g_cur[set * NNODES + d], 1);
    g_csr[pos] = s;
}

// ------------- W split+transpose with kv-interleave column permutation -----
__global__ void conv_w(const float* __restrict__ W1, const float* __restrict__ W2) {
    int idx = blockIdx.x * blockDim.x + threadIdx.x;
    if (idx >= 2000 * 160) return;
    int k = idx / 160, n = idx - k * 160;
    const float* Wsrc = (n < 80) ? W1 : W2;
    int nn = (n < 80) ? n : n - 80;
    int s = nn / 20, o = nn % 20;
    float w = Wsrc[((size_t)s * 2000 + k) * 20 + o];
    __nv_bfloat16 h = __float2bfloat16(w);
    int nperm = ((n < 80) ? 0 : 80) + qkvpos(nn);
    g_wt_hi[(size_t)k * 160 + nperm] = h;
    g_wt_lo[(size_t)k * 160 + nperm] = __float2bfloat16(w - __bfloat162float(h));
}

// ------------------------- big GEMM via mma.sync bf16-split ----------------
// Fully async-pipelined: A fp32 staged via cp.async (zero-fill OOB), B double-
// buffered via cp.async; chunk ch+1 loads issue before compute of ch.
#define SA_STRIDE 168
#define SB_STRIDE 168
#define OFF_ARAW 0
#define OFF_A    40960
#define OFF_B0   (40960 + 43008)
#define OFF_B1   (OFF_B0 + 53760)
#define SMEM_MMA (OFF_B1 + 53760)   /* 191488 B */

__global__ void __launch_bounds__(256)
gemm_big_mma(const float* __restrict__ A,
             const float* __restrict__ b1, const float* __restrict__ b2,
             float* __restrict__ outA, float* __restrict__ outB) {
    extern __shared__ __align__(16) char dsm[];
    float* sAraw = (float*)(dsm + OFF_ARAW);
    __nv_bfloat16* sA = (__nv_bfloat16*)(dsm + OFF_A);
    __shared__ float s_bias[160];

    const int tid = threadIdx.x, wid = tid >> 5, lane = tid & 31;
    const int rowbase = blockIdx.x * 128;
    if (tid < 160) {
        int g = tid / 80, c = tid % 80;
        float bv = (g == 0) ? b1[c] : b2[c];
        s_bias[g * 80 + qkvpos(c)] = bv;
    }

    float acc[20][4];
#pragma unroll
    for (int t = 0; t < 20; t++)
#pragma unroll
        for (int i = 0; i < 4; i++) acc[t][i] = 0.f;

    const int r_in = lane & 7, blkb = (lane >> 3) & 1, kh = (lane >> 4) & 1;
    const uint32_t aBase =
        smem_u32(sA) + (uint32_t)((wid * 16 + blkb * 8 + r_in) * SA_STRIDE + kh * 8) * 2;
    const uint32_t sb0 = smem_u32(dsm + OFF_B0);
    const uint32_t sb1 = smem_u32(dsm + OFF_B1);
    const uint32_t arawBase = smem_u32(sAraw);

    const int a0off[7] = {0, 32, 64, 16, 48, 80, 112};
    const int a1off[7] = {16, 48, 0, 32, 64, 96, 128};
    const int browt[7] = {0, 32, 64, 96, 128, 0, 32};

    // ---- stage issuers ----
    auto stage_B = [&](int ch, uint32_t sbbuf) {
        const int k0 = ch * 80;
#pragma unroll
        for (int it = 0; it < 13; it++) {
            int q = tid + it * 256;
            if (q < 3200) {
                int row = q / 20, c16 = q - row * 20;
                int kk = (row >= 80) ? row - 80 : row;
                const __nv_bfloat16* src =
                    ((row >= 80) ? g_wt_lo : g_wt_hi) + (size_t)(k0 + kk) * 160 + c16 * 8;
                uint32_t dst = sbbuf + (uint32_t)(row * SB_STRIDE + c16 * 8) * 2;
                asm volatile("cp.async.ca.shared.global [%0], [%1], 16;"
                             :: "r"(dst), "l"(src));
            }
        }
    };
    auto stage_Araw = [&](int ch) {
        const int k0 = ch * 80;
#pragma unroll
        for (int it = 0; it < 10; it++) {
            int q = tid + it * 256;            // 0..2559: 128 rows x 20 16B-chunks
            int r = q / 20, f = q - r * 20;
            int row = rowbase + r;
            const float* src = A + (size_t)row * 2000 + k0 + f * 4;
            uint32_t dst = arawBase + (uint32_t)(r * 80 + f * 4) * 4;
            unsigned sz = (row < NNODES) ? 16u : 0u;   // zero-fill OOB rows
            asm volatile("cp.async.ca.shared.global [%0], [%1], 16, %2;"
                         :: "r"(dst), "l"(src), "r"(sz));
        }
    };

    // prologue: chunk 0 loads
    stage_B(0, sb0);
    stage_Araw(0);
    asm volatile("cp.async.commit_group;" ::: "memory");

    for (int ch = 0; ch < 25; ch++) {
        asm volatile("cp.async.wait_group 0;" ::: "memory");
        __syncthreads();   // loads of ch landed; prev compute done (sA safe to overwrite)
        // ---- convert Araw fp32 -> bf16 hi/lo sections in sA ----
#pragma unroll
        for (int it = 0; it < 10; it++) {
            int q = tid + it * 256;
            int r = q / 20, f = q - r * 20;
            const float* rpR = sAraw + r * 80 + f * 4;
            float x = rpR[0], y = rpR[1], z = rpR[2], w = rpR[3];
            float l0, l1, l2, l3;
            uint32_t h0 = packbf2(x, y, &l0, &l1);
            uint32_t h1 = packbf2(z, w, &l2, &l3);
            uint32_t p0 = packbf2s(l0, l1), p1 = packbf2s(l2, l3);
            int k = f * 4;
            __nv_bfloat16* rp = sA + r * SA_STRIDE;
            *(uint32_t*)(rp + k) = h0;
            *(uint32_t*)(rp + k + 2) = h1;
            *(uint32_t*)(rp + 80 + k) = p0;
            *(uint32_t*)(rp + 82 + k) = p1;
        }
        __syncthreads();   // sA ready; Araw consumed
        if (ch < 24) {     // issue next chunk's loads; they overlap compute below
            stage_B(ch + 1, ((ch + 1) & 1) ? sb1 : sb0);
            stage_Araw(ch + 1);
            asm volatile("cp.async.commit_group;" ::: "memory");
        }
        const uint32_t sbc = (ch & 1) ? sb1 : sb0;
        const uint32_t bBase2 = sbc + (uint32_t)((lane & 15) * SB_STRIDE) * 2;
        const uint32_t bBase4 = sbc + (uint32_t)(lane * SB_STRIDE) * 2;
        // ---- compute ----
#pragma unroll
        for (int jp = 0; jp < 7; jp++) {
            uint32_t a0, a1, a2, a3, c0, c1, c2, c3;
            asm volatile(
                "ldmatrix.sync.aligned.m8n8.x4.shared.b16 {%0,%1,%2,%3}, [%4];"
                : "=r"(a0), "=r"(a1), "=r"(a2), "=r"(a3)
                : "r"(aBase + (uint32_t)a0off[jp] * 2));
            asm volatile(
                "ldmatrix.sync.aligned.m8n8.x4.shared.b16 {%0,%1,%2,%3}, [%4];"
                : "=r"(c0), "=r"(c1), "=r"(c2), "=r"(c3)
                : "r"(aBase + (uint32_t)a1off[jp] * 2));
            const uint32_t bb = bBase4 + (uint32_t)(browt[jp] * SB_STRIDE) * 2;
#pragma unroll
            for (int t = 0; t < 20; t++) {
                uint32_t b0, b1, b2, b3;
                asm volatile(
                    "ldmatrix.sync.aligned.m8n8.x4.trans.shared.b16 {%0,%1,%2,%3}, [%4];"
                    : "=r"(b0), "=r"(b1), "=r"(b2), "=r"(b3)
                    : "r"(bb + (uint32_t)t * 16));
                asm volatile(
                    "mma.sync.aligned.m16n8k16.row.col.f32.bf16.bf16.f32 "
                    "{%0,%1,%2,%3}, {%4,%5,%6,%7}, {%8,%9}, {%0,%1,%2,%3};"
                    : "+f"(acc[t][0]), "+f"(acc[t][1]), "+f"(acc[t][2]), "+f"(acc[t][3])
                    : "r"(a0), "r"(a1), "r"(a2), "r"(a3), "r"(b0), "r"(b1));
                asm volatile(
                    "mma.sync.aligned.m16n8k16.row.col.f32.bf16.bf16.f32 "
                    "{%0,%1,%2,%3}, {%4,%5,%6,%7}, {%8,%9}, {%0,%1,%2,%3};"
                    : "+f"(acc[t][0]), "+f"(acc[t][1]), "+f"(acc[t][2]), "+f"(acc[t][3])
                    : "r"(c0), "r"(c1), "r"(c2), "r"(c3), "r"(b2), "r"(b3));
            }
        }
        {
            uint32_t a0, a1, a2, a3;
            asm volatile(
                "ldmatrix.sync.aligned.m8n8.x4.shared.b16 {%0,%1,%2,%3}, [%4];"
                : "=r"(a0), "=r"(a1), "=r"(a2), "=r"(a3)
                : "r"(aBase + 144u * 2));
            const uint32_t bb = bBase2 + (uint32_t)(64 * SB_STRIDE) * 2;
#pragma unroll
            for (int t = 0; t < 20; t++) {
                uint32_t b0, b1;
                asm volatile(
                    "ldmatrix.sync.aligned.m8n8.x2.trans.shared.b16 {%0,%1}, [%2];"
                    : "=r"(b0), "=r"(b1)
                    : "r"(bb + (uint32_t)t * 16));
                asm volatile(
                    "mma.sync.aligned.m16n8k16.row.col.f32.bf16.bf16.f32 "
                    "{%0,%1,%2,%3}, {%4,%5,%6,%7}, {%8,%9}, {%0,%1,%2,%3};"
                    : "+f"(acc[t][0]), "+f"(acc[t][1]), "+f"(acc[t][2]), "+f"(acc[t][3])
                    : "r"(a0), "r"(a1), "r"(a2), "r"(a3), "r"(b0), "r"(b1));
            }
        }
        __syncthreads();
    }

    const int r0 = rowbase + wid * 16 + lane / 4;
    const int r1 = r0 + 8;
    const int cb = (lane & 3) * 2;
#pragma unroll
    for (int t = 0; t < 20; t++) {
        int col = t * 8 + cb;
        float* base = (col < 80) ? outA : outB;
        int cc = (col < 80) ? col : col - 80;
        float bia0 = s_bias[col], bia1 = s_bias[col + 1];
        if (r0 < NNODES)
            *(float2*)(base + (size_t)r0 * 80 + cc) =
                make_float2(acc[t][0] + bia0, acc[t][1] + bia1);
        if (r1 < NNODES)
            *(float2*)(base + (size_t)r1 * 80 + cc) =
                make_float2(acc[t][2] + bia0, acc[t][3] + bia1);
    }
}

// --------------- fused small GEMMs (+ optional bn_fc block range) ----------
__global__ void __launch_bounds__(256)
gemm_small3(const float* __restrict__ preA, const float* __restrict__ preB,
            const float* __restrict__ stX, const float* __restrict__ stY,
            const float* __restrict__ g1, const float* __restrict__ be1,
            const float* __restrict__ g2, const float* __restrict__ be2,
            const float* __restrict__ Wc3, const float* __restrict__ bc3,
            float* __restrict__ outC,
            const float* __restrict__ Wc1, const float* __restrict__ bc1,
            float* __restrict__ outA,
            const float* __restrict__ Wc2, const float* __restrict__ bc2,
            float* __restrict__ outB,
            int nsets,
            const float* __restrict__ bnPre, const float* __restrict__ bnStats,
            const float* __restrict__ bnG, const float* __restrict__ bnB,
            float* __restrict__ bnDst, int bnOff) {
    const int bnStart = nsets * GB_SM;
    if ((int)blockIdx.x >= bnStart) {
        int idx = (blockIdx.x - bnStart) * 256 + threadIdx.x;
        if (idx >= NNODES * 20) return;
        int n = idx / 20, c = idx % 20;
        const float invN = 1.f / (float)NNODES;
        float mu = bnStats[c] * invN;
        float var = bnStats[20 + c] * invN - mu * mu;
        float scv = bnG[c] * rsqrtf(var + EPS_BN);
        float v = (bnPre[idx] - mu) * scv + bnB[c];
        v = (v >= 0.f) ? v : LSLOPE * v;
        bnDst[(size_t)n * 100 + bnOff + c] = v;
        return;
    }
    const int set = blockIdx.x / GB_SM;
    const int bi = blockIdx.x - set * GB_SM;
    const bool swap = (set == 2);
    const float* preX = swap ? preB : preA;
    const float* preY = swap ? preA : preB;
    const float* statsX = swap ? stY : stX;
    const float* statsY = swap ? stX : stY;
    const float* gX = swap ? g2 : g1;
    const float* betX = swap ? be2 : be1;
    const float* gY = swap ? g1 : g2;
    const float* betY = swap ? be1 : be2;
    const float* W = (set == 0) ? Wc3 : ((set == 1) ? Wc1 : Wc2);
    const float* b = (set == 0) ? bc3 : ((set == 1) ? bc1 : bc2);
    float* out = (set == 0) ? outC : ((set == 1) ? outA : outB);

    __shared__ __align__(8) float sW[40][80];
    __shared__ float sb[80];
    __shared__ float sMu[40], sScv[40], sBeta[40];
    const int tid = threadIdx.x;
    for (int l = tid; l < 3200; l += 256) {
        int s = l / 800, rem = l % 800, k = rem / 20, o = rem % 20;
        sW[k][qkvpos(s * 20 + o)] = W[l];
    }
    if (tid < 80) sb[qkvpos(tid)] = b[tid];
    if (tid < 40) {
        const float invN = 1.f / (float)NNODES;
        int c = tid % 20;
        const float* st = (tid < 20) ? statsX : statsY;
        const float* gg = (tid < 20) ? gX : gY;
        const float* bb = (tid < 20) ? betX : betY;
        float mu = st[c] * invN;
        float var = st[20 + c] * invN - mu * mu;
        sMu[tid] = mu;
        sScv[tid] = gg[c] * rsqrtf(var + EPS_BN);
        sBeta[tid] = bb[c];
    }
    __syncthreads();

    const int row = bi * 128 + (tid >> 1);
    const int cb = (tid & 1) * 40;
    if (row >= NNODES) return;

    float a[40];
    {
        const float4* pa = (const float4*)(preX + (size_t)row * 20);
        const float4* pb = (const float4*)(preY + (size_t)row * 20);
        float4 va[5], vb[5];
#pragma unroll
        for (int i = 0; i < 5; i++) va[i] = pa[i];
#pragma unroll
        for (int i = 0; i < 5; i++) vb[i] = pb[i];
#pragma unroll
        for (int i = 0; i < 5; i++) {
            a[4 * i]     = va[i].x; a[4 * i + 1] = va[i].y;
            a[4 * i + 2] = va[i].z; a[4 * i + 3] = va[i].w;
            a[20 + 4 * i] = vb[i].x; a[21 + 4 * i] = vb[i].y;
            a[22 + 4 * i] = vb[i].z; a[23 + 4 * i] = vb[i].w;
        }
    }
#pragma unroll
    for (int k = 0; k < 40; k++) {
        float v = (a[k] - sMu[k]) * sScv[k] + sBeta[k];
        a[k] = (v >= 0.f) ? v : LSLOPE * v;
    }

    unsigned long long acc[20];
#pragma unroll
    for (int c = 0; c < 20; c++) acc[c] = 0ull;
#pragma unroll 8
    for (int k = 0; k < 40; k++) {
        unsigned long long a2 = pack2(a[k], a[k]);
        const unsigned long long* wrow = (const unsigned long long*)(&sW[k][cb]);
#pragma unroll
        for (int c = 0; c < 20; c++) acc[c] = ffma2(a2, wrow[c], acc[c]);
    }

    float res[40];
#pragma unroll
    for (int c = 0; c < 20; c++) {
        res[2 * c]     = __uint_as_float((unsigned)(acc[c] & 0xffffffffull)) + sb[cb + 2 * c];
        res[2 * c + 1] = __uint_as_float((unsigned)(acc[c] >> 32)) + sb[cb + 2 * c + 1];
    }
    float* dst = out + (size_t)row * 80 + cb;
#pragma unroll
    for (int c = 0; c < 40; c += 4)
        *(float4*)(dst + c) = make_float4(res[c], res[c + 1], res[c + 2], res[c + 3]);
}

// ---------- CSR aggregation: channel-pair lanes, 2 edges per warp-step ------
__global__ void __launch_bounds__(256)
agg_csr3(const float* __restrict__ q0, int nb0, float* __restrict__ p0, float* __restrict__ s0,
         const float* __restrict__ q1, int nb1, float* __restrict__ p1, float* __restrict__ s1,
         const float* __restrict__ q2, int nb2, float* __restrict__ p2, float* __restrict__ s2) {
    const int set = blockIdx.x / GA_BLK;
    const int bi = blockIdx.x - set * GA_BLK;
    const float* qkv = (set == 0) ? q0 : ((set == 1) ? q1 : q2);
    float* pre = (set == 0) ? p0 : ((set == 1) ? p1 : p2);
    float* stats = (set == 0) ? s0 : ((set == 1) ? s1 : s2);
    const int nbase = (set == 0) ? nb0 : ((set == 1) ? nb1 : nb2);

    const int wid = threadIdx.x >> 5, lane = threadIdx.x & 31;
    const int n = bi * 8 + wid;
    const int half = lane >> 4;
    const int hl = lane & 15;
    const bool act = hl < 10;
    const int cp = hl;

    __shared__ float sst[2][8][20];
    for (int l = threadIdx.x; l < 320; l += 256) ((float*)sst)[l] = 0.f;
    __syncthreads();

    if (n < NNODES) {
        const int gi = nbase + n;
        const int off0 = g_off[gi], off1 = g_off[gi + 1];
        float2 q2v = make_float2(0.f, 0.f);
        if (act) {
            q2v = *(const float2*)(qkv + (size_t)n * 80 + 2 * cp);
            q2v.x *= 0.22360679774997896f;
            q2v.y *= 0.22360679774997896f;
        }
        const uint32_t kvf = 20 + 4 * cp;
        float accx = 0.f, accy = 0.f, denom = 0.f;
        int p = off0;
        for (; p + 4 <= off1; p += 4) {
            int sA = g_csr[p + half];
            int sB = g_csr[p + 2 + half];
            float4 kv0 = act ? *(const float4*)(qkv + (size_t)sA * 80 + kvf)
                             : make_float4(0.f, 0.f, 0.f, 0.f);
            float4 kv1 = act ? *(const float4*)(qkv + (size_t)sB * 80 + kvf)
                             : make_float4(0.f, 0.f, 0.f, 0.f);
            float d0 = q2v.x * kv0.x + q2v.y * kv0.z;
            float d1 = q2v.x * kv1.x + q2v.y * kv1.z;
#pragma unroll
            for (int o = 8; o; o >>= 1) {
                d0 += __shfl_xor_sync(~0u, d0, o);
                d1 += __shfl_xor_sync(~0u, d1, o);
            }
            float e0 = __expf(d0), e1 = __expf(d1);
            denom += e0 + e1;
            accx += e0 * kv0.y + e1 * kv1.y;
            accy += e0 * kv0.w + e1 * kv1.w;
        }
        for (; p < off1; p += 2) {
            bool ea = (p + half) < off1;
            int sA = ea ? g_csr[p + half] : 0;
            float4 kv0 = (act && ea) ? *(const float4*)(qkv + (size_t)sA * 80 + kvf)
                                     : make_float4(0.f, 0.f, 0.f, 0.f);
            float d0 = q2v.x * kv0.x + q2v.y * kv0.z;
#pragma unroll
            for (int o = 8; o; o >>= 1) d0 += __shfl_xor_sync(~0u, d0, o);
            float e0 = ea ? __expf(d0) : 0.f;
            denom += e0;
            accx += e0 * kv0.y;
            accy += e0 * kv0.w;
        }
        accx += __shfl_xor_sync(~0u, accx, 16);
        accy += __shfl_xor_sync(~0u, accy, 16);
        denom += __shfl_xor_sync(~0u, denom, 16);
        float inv = 1.f / fmaxf(denom, 1e-16f);
        if (act && half == 0) {
            float2 sk = *(const float2*)(qkv + (size_t)n * 80 + 60 + 2 * cp);
            float rx = accx * inv + sk.x;
            float ry = accy * inv + sk.y;
            *(float2*)(pre + (size_t)n * 20 + 2 * cp) = make_float2(rx, ry);
            sst[0][wid][2 * cp] = rx;
            sst[0][wid][2 * cp + 1] = ry;
            sst[1][wid][2 * cp] = rx * rx;
            sst[1][wid][2 * cp + 1] = ry * ry;
        }
    }
    __syncthreads();
    if (threadIdx.x < 40) {
        int which = threadIdx.x / 20, cc = threadIdx.x % 20;
        float t = 0.f;
#pragma unroll
        for (int w = 0; w < 8; w++) t += sst[which][w][cc];
        atomicAdd(&stats[which * 20 + cc], t);
    }
}

// ------------- final FC with fused last-layer BN (cols 80..99 inline) ------
__global__ void __launch_bounds__(128)
fc_bn_kernel(const float* __restrict__ W, const float* __restrict__ b,
             const float* __restrict__ preC, const float* __restrict__ stats,
             const float* __restrict__ gamma, const float* __restrict__ beta,
             float* __restrict__ out) {
    __shared__ float sw[200];
    __shared__ float sMu[20], sScv[20], sBeta[20];
    for (int l = threadIdx.x; l < 200; l += blockDim.x) sw[l] = W[l];
    if (threadIdx.x < 20) {
        const float invN = 1.f / (float)NNODES;
        int c = threadIdx.x;
        float mu = stats[c] * invN;
        float var = stats[20 + c] * invN - mu * mu;
        sMu[c] = mu;
        sScv[c] = gamma[c] * rsqrtf(var + EPS_BN);
        sBeta[c] = beta[c];
    }
    __syncthreads();
    int n = blockIdx.x * blockDim.x + threadIdx.x;
    if (n >= NNODES) return;
    float a0 = b[0], a1 = b[1];
    const float4* fp = (const float4*)(g_fc + (size_t)n * 100);
#pragma unroll
    for (int i = 0; i < 20; i++) {   // cols 0..79
        float4 f = fp[i];
        int c = 4 * i;
        a0 += f.x * sw[2 * c] + f.y * sw[2 * c + 2] + f.z * sw[2 * c + 4] + f.w * sw[2 * c + 6];
        a1 += f.x * sw[2 * c + 1] + f.y * sw[2 * c + 3] + f.z * sw[2 * c + 5] + f.w * sw[2 * c + 7];
    }
    const float4* pp = (const float4*)(preC + (size_t)n * 20);
#pragma unroll
    for (int i = 0; i < 5; i++) {    // cols 80..99 from BN(preC)
        float4 f = pp[i];
        float vv[4] = {f.x, f.y, f.z, f.w};
#pragma unroll
        for (int j = 0; j < 4; j++) {
            int c = 4 * i + j;
            float v = (vv[j] - sMu[c]) * sScv[c] + sBeta[c];
            v = (v >= 0.f) ? v : LSLOPE * v;
            int col = 80 + c;
            a0 += v * sw[2 * col];
            a1 += v * sw[2 * col + 1];
        }
    }
    out[2 * n] = a0;
    out[2 * n + 1] = a1;
}

// ------------------------- host orchestration -------------------------
extern "C" void kernel_launch(void* const* d_in, const int* in_sizes, int n_in,
                              void* d_out, int out_size) {
    (void)in_sizes; (void)n_in; (void)out_size;
    const float* features = (const float*)d_in[0];
    const int* edge_index = (const int*)d_in[3];
    const int* same2      = (const int*)d_in[4];
    const int* diff2      = (const int*)d_in[5];
    const float* c1_W0 = (const float*)d_in[6];
    const float* c1_b0 = (const float*)d_in[7];
    const float* c2_W0 = (const float*)d_in[8];
    const float* c2_b0 = (const float*)d_in[9];
    const float* c1_W  = (const float*)d_in[10];
    const float* c1_b  = (const float*)d_in[11];
    const float* c2_W  = (const float*)d_in[12];
    const float* c2_b  = (const float*)d_in[13];
    const float* c3_W  = (const float*)d_in[14];
    const float* c3_b  = (const float*)d_in[15];
    const float* bn1_g = (const float*)d_in[16];
    const float* bn1_b = (const float*)d_in[17];
    const float* bn2_g = (const float*)d_in[18];
    const float* bn2_b = (const float*)d_in[19];
    const float* bn3_g = (const float*)d_in[20];
    const float* bn3_b = (const float*)d_in[21];
    const float* fc_W  = (const float*)d_in[22];
    const float* fc_b  = (const float*)d_in[23];
    float* out = (float*)d_out;

    float *qkvA, *qkvB, *qkvC, *preA, *preB, *preC, *fcb, *stats;
    cudaGetSymbolAddress((void**)&qkvA, g_qkvA);
    cudaGetSymbolAddress((void**)&qkvB, g_qkvB);
    cudaGetSymbolAddress((void**)&qkvC, g_qkvC);
    cudaGetSymbolAddress((void**)&preA, g_preA);
    cudaGetSymbolAddress((void**)&preB, g_preB);
    cudaGetSymbolAddress((void**)&preC, g_preC);
    cudaGetSymbolAddress((void**)&fcb, g_fc);
    cudaGetSymbolAddress((void**)&stats, g_stats);

    const int G3E = (3 * NEDGE + 255) / 256;

    cudaFuncSetAttribute(gemm_big_mma, cudaFuncAttributeMaxDynamicSharedMemorySize,
                         SMEM_MMA);

    // lazily-created side stream + events (resources only; identical work per call)
    static cudaStream_t s2 = nullptr;
    static cudaEvent_t evFork = nullptr, evJoin = nullptr;
    if (!s2) {
        cudaStreamCreateWithFlags(&s2, cudaStreamNonBlocking);
        cudaEventCreateWithFlags(&evFork, cudaEventDisableTiming);
        cudaEventCreateWithFlags(&evJoin, cudaEventDisableTiming);
    }

    // ---- fork: CSR build on s2, conv_w + big GEMM on default ----
    cudaEventRecord(evFork, 0);
    cudaStreamWaitEvent(s2, evFork, 0);

    zero_all<<<(NN3 + 255) / 256, 256, 0, s2>>>();
    hist_kernel<<<G3E, 256, 0, s2>>>(same2, diff2, edge_index);
    scanA<<<SCAN_BLOCKS, 1024, 0, s2>>>();
    scanB<<<1, 256, 0, s2>>>();
    scanC<<<SCAN_BLOCKS, 1024, 0, s2>>>();
    scatter_kernel<<<G3E, 256, 0, s2>>>(same2, diff2, edge_index);
    cudaEventRecord(evJoin, s2);

    conv_w<<<(2000 * 160 + 255) / 256, 256>>>(c1_W0, c2_W0);
    gemm_big_mma<<<GB_SM, 256, SMEM_MMA>>>(features, c1_b0, c2_b0, qkvA, qkvB);

    cudaStreamWaitEvent(0, evJoin, 0);  // join before first agg

    // ---- layer 0 ----
    agg_csr3<<<2 * GA_BLK, 256>>>(qkvA, 0, preA, stats + 0 * 40,
                                  qkvB, NNODES, preB, stats + 1 * 40,
                                  qkvA, 0, preA, stats + 0 * 40);

    for (int L = 0; L <= 4; L++) {
        const float* stX = stats + (3 * L) * 40;
        const float* stY = stats + (3 * L + 1) * 40;
        const float* g1 = bn1_g + L * 20; const float* b1 = bn1_b + L * 20;
        const float* g2 = bn2_g + L * 20; const float* b2 = bn2_b + L * 20;
        const int nsets = (L < 4) ? 3 : 1;
        const int bnBlocks = (L > 0) ? GN_BLK : 0;

        gemm_small3<<<nsets * GB_SM + bnBlocks, 256>>>(
            preA, preB, stX, stY, g1, b1, g2, b2,
            c3_W + (size_t)L * 3200, c3_b + (size_t)L * 80, qkvC,
            c1_W + (size_t)L * 3200, c1_b + (size_t)L * 80, qkvA,
            c2_W + (size_t)L * 3200, c2_b + (size_t)L * 80, qkvB,
            nsets,
            preC, stats + (3 * (L - 1) + 2) * 40,
            bn3_g + (L - 1) * 20, bn3_b + (L - 1) * 20, fcb, (L - 1) * 20);

        if (L < 4) {
            agg_csr3<<<3 * GA_BLK, 256>>>(qkvC, 2 * NNODES, preC, stats + (3 * L + 2) * 40,
                                          qkvA, 0, preA, stats + (3 * L + 3) * 40,
                                          qkvB, NNODES, preB, stats + (3 * L + 4) * 40);
        } else {
            agg_csr3<<<GA_BLK, 256>>>(qkvC, 2 * NNODES, preC, stats + (3 * L + 2) * 40,
                                      qkvC, 2 * NNODES, preC, stats + (3 * L + 2) * 40,
                                      qkvC, 2 * NNODES, preC, stats + (3 * L + 2) * 40);
        }
    }

    // final FC with fused last-layer BN (slot 14)
    fc_bn_kernel<<<(NNODES + 127) / 128, 128>>>(fc_W, fc_b, preC, stats + 14 * 40,
                                                bn3_g + 80, bn3_b + 80, out);
}

// round 15
// speedup vs baseline: 1.7228x; 1.0806x over previous
#include <cuda_runtime.h>
#include <cuda_bf16.h>
#include <cstdint>

#define NNODES 50000
#define NEDGE  1000000
#define DIN0   2000
#define EPS_BN 1e-5f
#define LSLOPE 0.01f
#define NN3    150000
#define SCAN_BLOCKS 147
#define GA_BLK 6250
#define GB_SM  391
#define GN_BLK 3907

// qkv row layout (80 floats): [ q(0..19) | k0 v0 k1 v1 .. k19 v19 (20..59) | skip(60..79) ]

// ------------------------- scratch (device globals, zero-init) -------------
__device__ float g_qkvA[NNODES * 80];
__device__ float g_qkvB[NNODES * 80];
__device__ float g_qkvC[NNODES * 80];
__device__ float g_preA[NNODES * 20];
__device__ float g_preB[NNODES * 20];
__device__ float g_preC[NNODES * 20];
__device__ float g_fc[NNODES * 100];
__device__ float g_stats[15 * 40];
__device__ __nv_bfloat16 g_wt_hi[2000 * 160];
__device__ __nv_bfloat16 g_wt_lo[2000 * 160];
// CSR scratch
__device__ int g_cnt[NN3];
__device__ int g_off[NN3 + 1];
__device__ int g_cur[NN3];
__device__ int g_csr[3 * NEDGE];
__device__ int g_partraw[SCAN_BLOCKS];
__device__ int g_part[SCAN_BLOCKS];

// ------------------------- helpers -------------------------
__device__ __forceinline__ uint32_t smem_u32(const void* p) {
    uint32_t a;
    asm("{ .reg .u64 t; cvta.to.shared.u64 t, %1; cvt.u32.u64 %0, t; }"
        : "=r"(a) : "l"(p));
    return a;
}
__device__ __forceinline__ uint32_t packbf2(float a, float b, float* lo_a, float* lo_b) {
    __nv_bfloat16 ha = __float2bfloat16(a), hb = __float2bfloat16(b);
    *lo_a = a - __bfloat162float(ha);
    *lo_b = b - __bfloat162float(hb);
    __nv_bfloat162 p; p.x = ha; p.y = hb;
    return *(uint32_t*)&p;
}
__device__ __forceinline__ uint32_t packbf2s(float a, float b) {
    __nv_bfloat162 p; p.x = __float2bfloat16(a); p.y = __float2bfloat16(b);
    return *(uint32_t*)&p;
}
__device__ __forceinline__ int qkvpos(int c) {
    if (c < 20) return c;
    if (c < 40) return 2 * c - 20;
    if (c < 60) return 2 * c - 59;
    return c;
}

// ------------------------- CSR build -------------------------
__global__ void zero_all() {
    int i = blockIdx.x * blockDim.x + threadIdx.x;
    if (i < NN3) g_cnt[i] = 0;
    if (i < 15 * 40) g_stats[i] = 0.f;
}
__global__ void hist_kernel(const int* __restrict__ e0, const int* __restrict__ e1,
                            const int* __restrict__ e2) {
    int i = blockIdx.x * blockDim.x + threadIdx.x;
    if (i >= 3 * NEDGE) return;
    int set = i / NEDGE, e = i - set * NEDGE;
    const int* ei = (set == 0) ? e0 : ((set == 1) ? e1 : e2);
    atomicAdd(&g_cnt[set * NNODES + ei[NEDGE + e]], 1);
}
__global__ void __launch_bounds__(1024) scanA() {
    int gid = blockIdx.x * 1024 + threadIdx.x;
    int v = (gid < NN3) ? g_cnt[gid] : 0;
#pragma unroll
    for (int o = 16; o; o >>= 1) v += __shfl_xor_sync(~0u, v, o);
    __shared__ int sw[32];
    if ((threadIdx.x & 31) == 0) sw[threadIdx.x >> 5] = v;
    __syncthreads();
    if (threadIdx.x < 32) {
        int t = sw[threadIdx.x];
#pragma unroll
        for (int o = 16; o; o >>= 1) t += __shfl_xor_sync(~0u, t, o);
        if (threadIdx.x == 0) g_partraw[blockIdx.x] = t;
    }
}
__global__ void scanB() {
    __shared__ int sp[SCAN_BLOCKS + 1];
    int tid = threadIdx.x;
    if (tid < SCAN_BLOCKS) sp[tid + 1] = g_partraw[tid];
    if (tid == 0) sp[0] = 0;
    __syncthreads();
    if (tid == 0)
        for (int b = 1; b <= SCAN_BLOCKS; b++) sp[b] += sp[b - 1];
    __syncthreads();
    if (tid < SCAN_BLOCKS) g_part[tid] = sp[tid];
}
__global__ void __launch_bounds__(1024) scanC() {
    __shared__ int sdat[1024];
    int tid = threadIdx.x;
    int gid = blockIdx.x * 1024 + tid;
    int v = (gid < NN3) ? g_cnt[gid] : 0;
    sdat[tid] = v;
    __syncthreads();
    for (int o = 1; o < 1024; o <<= 1) {
        int t = (tid >= o) ? sdat[tid - o] : 0;
        __syncthreads();
        sdat[tid] += t;
        __syncthreads();
    }
    int excl = sdat[tid] - v + g_part[blockIdx.x];
    if (gid < NN3) { g_off[gid] = excl; g_cur[gid] = excl; }
    if (gid == 0) g_off[NN3] = 3 * NEDGE;
}
__global__ void scatter_kernel(const int* __restrict__ e0, const int* __restrict__ e1,
                               const int* __restrict__ e2) {
    int i = blockIdx.x * blockDim.x + threadIdx.x;
    if (i >= 3 * NEDGE) return;
    int set = i / NEDGE, e = i - set * NEDGE;
    const int* ei = (set == 0) ? e0 : ((set == 1) ? e1 : e2);
    int s = ei[e], d = ei[NEDGE + e];
    int pos = atomicAdd(&g_cur[set * NNODES + d], 1);
    g_csr[pos] = s;
}

// ------------- W split+transpose with kv-interleave column permutation -----
__global__ void conv_w(const float* __restrict__ W1, const float* __restrict__ W2) {
    int idx = blockIdx.x * blockDim.x + threadIdx.x;
    if (idx >= 2000 * 160) return;
    int k = idx / 160, n = idx - k * 160;
    const float* Wsrc = (n < 80) ? W1 : W2;
    int nn = (n < 80) ? n : n - 80;
    int s = nn / 20, o = nn % 20;
    float w = Wsrc[((size_t)s * 2000 + k) * 20 + o];
    __nv_bfloat16 h = __float2bfloat16(w);
    int nperm = ((n < 80) ? 0 : 80) + qkvpos(nn);
    g_wt_hi[(size_t)k * 160 + nperm] = h;
    g_wt_lo[(size_t)k * 160 + nperm] = __float2bfloat16(w - __bfloat162float(h));
}

// ------------------------- big GEMM via mma.sync bf16-split ----------------
#define SA_STRIDE 168
#define SB_STRIDE 168
#define OFF_ARAW 0
#define OFF_A    40960
#define OFF_B0   (40960 + 43008)
#define OFF_B1   (OFF_B0 + 53760)
#define SMEM_MMA (OFF_B1 + 53760)

__global__ void __launch_bounds__(256)
gemm_big_mma(const float* __restrict__ A,
             const float* __restrict__ b1, const float* __restrict__ b2,
             float* __restrict__ outA, float* __restrict__ outB) {
    extern __shared__ __align__(16) char dsm[];
    float* sAraw = (float*)(dsm + OFF_ARAW);
    __nv_bfloat16* sA = (__nv_bfloat16*)(dsm + OFF_A);
    __shared__ float s_bias[160];

    const int tid = threadIdx.x, wid = tid >> 5, lane = tid & 31;
    const int rowbase = blockIdx.x * 128;
    if (tid < 160) {
        int g = tid / 80, c = tid % 80;
        float bv = (g == 0) ? b1[c] : b2[c];
        s_bias[g * 80 + qkvpos(c)] = bv;
    }

    float acc[20][4];
#pragma unroll
    for (int t = 0; t < 20; t++)
#pragma unroll
        for (int i = 0; i < 4; i++) acc[t][i] = 0.f;

    const int r_in = lane & 7, blkb = (lane >> 3) & 1, kh = (lane >> 4) & 1;
    const uint32_t aBase =
        smem_u32(sA) + (uint32_t)((wid * 16 + blkb * 8 + r_in) * SA_STRIDE + kh * 8) * 2;
    const uint32_t sb0 = smem_u32(dsm + OFF_B0);
    const uint32_t sb1 = smem_u32(dsm + OFF_B1);
    const uint32_t arawBase = smem_u32(sAraw);

    const int a0off[7] = {0, 32, 64, 16, 48, 80, 112};
    const int a1off[7] = {16, 48, 0, 32, 64, 96, 128};
    const int browt[7] = {0, 32, 64, 96, 128, 0, 32};

    auto stage_B = [&](int ch, uint32_t sbbuf) {
        const int k0 = ch * 80;
#pragma unroll
        for (int it = 0; it < 13; it++) {
            int q = tid + it * 256;
            if (q < 3200) {
                int row = q / 20, c16 = q - row * 20;
                int kk = (row >= 80) ? row - 80 : row;
                const __nv_bfloat16* src =
                    ((row >= 80) ? g_wt_lo : g_wt_hi) + (size_t)(k0 + kk) * 160 + c16 * 8;
                uint32_t dst = sbbuf + (uint32_t)(row * SB_STRIDE + c16 * 8) * 2;
                asm volatile("cp.async.ca.shared.global [%0], [%1], 16;"
                             :: "r"(dst), "l"(src));
            }
        }
    };
    auto stage_Araw = [&](int ch) {
        const int k0 = ch * 80;
#pragma unroll
        for (int it = 0; it < 10; it++) {
            int q = tid + it * 256;
            int r = q / 20, f = q - r * 20;
            int row = rowbase + r;
            const float* src = A + (size_t)row * 2000 + k0 + f * 4;
            uint32_t dst = arawBase + (uint32_t)(r * 80 + f * 4) * 4;
            unsigned sz = (row < NNODES) ? 16u : 0u;
            asm volatile("cp.async.ca.shared.global [%0], [%1], 16, %2;"
                         :: "r"(dst), "l"(src), "r"(sz));
        }
    };

    stage_B(0, sb0);
    stage_Araw(0);
    asm volatile("cp.async.commit_group;" ::: "memory");

    for (int ch = 0; ch < 25; ch++) {
        asm volatile("cp.async.wait_group 0;" ::: "memory");
        __syncthreads();
#pragma unroll
        for (int it = 0; it < 10; it++) {
            int q = tid + it * 256;
            int r = q / 20, f = q - r * 20;
            const float* rpR = sAraw + r * 80 + f * 4;
            float x = rpR[0], y = rpR[1], z = rpR[2], w = rpR[3];
            float l0, l1, l2, l3;
            uint32_t h0 = packbf2(x, y, &l0, &l1);
            uint32_t h1 = packbf2(z, w, &l2, &l3);
            uint32_t p0 = packbf2s(l0, l1), p1 = packbf2s(l2, l3);
            int k = f * 4;
            __nv_bfloat16* rp = sA + r * SA_STRIDE;
            *(uint32_t*)(rp + k) = h0;
            *(uint32_t*)(rp + k + 2) = h1;
            *(uint32_t*)(rp + 80 + k) = p0;
            *(uint32_t*)(rp + 82 + k) = p1;
        }
        __syncthreads();
        if (ch < 24) {
            stage_B(ch + 1, ((ch + 1) & 1) ? sb1 : sb0);
            stage_Araw(ch + 1);
            asm volatile("cp.async.commit_group;" ::: "memory");
        }
        const uint32_t sbc = (ch & 1) ? sb1 : sb0;
        const uint32_t bBase2 = sbc + (uint32_t)((lane & 15) * SB_STRIDE) * 2;
        const uint32_t bBase4 = sbc + (uint32_t)(lane * SB_STRIDE) * 2;
#pragma unroll
        for (int jp = 0; jp < 7; jp++) {
            uint32_t a0, a1, a2, a3, c0, c1, c2, c3;
            asm volatile(
                "ldmatrix.sync.aligned.m8n8.x4.shared.b16 {%0,%1,%2,%3}, [%4];"
                : "=r"(a0), "=r"(a1), "=r"(a2), "=r"(a3)
                : "r"(aBase + (uint32_t)a0off[jp] * 2));
            asm volatile(
                "ldmatrix.sync.aligned.m8n8.x4.shared.b16 {%0,%1,%2,%3}, [%4];"
                : "=r"(c0), "=r"(c1), "=r"(c2), "=r"(c3)
                : "r"(aBase + (uint32_t)a1off[jp] * 2));
            const uint32_t bb = bBase4 + (uint32_t)(browt[jp] * SB_STRIDE) * 2;
#pragma unroll
            for (int t = 0; t < 20; t++) {
                uint32_t b0, b1, b2, b3;
                asm volatile(
                    "ldmatrix.sync.aligned.m8n8.x4.trans.shared.b16 {%0,%1,%2,%3}, [%4];"
                    : "=r"(b0), "=r"(b1), "=r"(b2), "=r"(b3)
                    : "r"(bb + (uint32_t)t * 16));
                asm volatile(
                    "mma.sync.aligned.m16n8k16.row.col.f32.bf16.bf16.f32 "
                    "{%0,%1,%2,%3}, {%4,%5,%6,%7}, {%8,%9}, {%0,%1,%2,%3};"
                    : "+f"(acc[t][0]), "+f"(acc[t][1]), "+f"(acc[t][2]), "+f"(acc[t][3])
                    : "r"(a0), "r"(a1), "r"(a2), "r"(a3), "r"(b0), "r"(b1));
                asm volatile(
                    "mma.sync.aligned.m16n8k16.row.col.f32.bf16.bf16.f32 "
                    "{%0,%1,%2,%3}, {%4,%5,%6,%7}, {%8,%9}, {%0,%1,%2,%3};"
                    : "+f"(acc[t][0]), "+f"(acc[t][1]), "+f"(acc[t][2]), "+f"(acc[t][3])
                    : "r"(c0), "r"(c1), "r"(c2), "r"(c3), "r"(b2), "r"(b3));
            }
        }
        {
            uint32_t a0, a1, a2, a3;
            asm volatile(
                "ldmatrix.sync.aligned.m8n8.x4.shared.b16 {%0,%1,%2,%3}, [%4];"
                : "=r"(a0), "=r"(a1), "=r"(a2), "=r"(a3)
                : "r"(aBase + 144u * 2));
            const uint32_t bb = bBase2 + (uint32_t)(64 * SB_STRIDE) * 2;
#pragma unroll
            for (int t = 0; t < 20; t++) {
                uint32_t b0, b1;
                asm volatile(
                    "ldmatrix.sync.aligned.m8n8.x2.trans.shared.b16 {%0,%1}, [%2];"
                    : "=r"(b0), "=r"(b1)
                    : "r"(bb + (uint32_t)t * 16));
                asm volatile(
                    "mma.sync.aligned.m16n8k16.row.col.f32.bf16.bf16.f32 "
                    "{%0,%1,%2,%3}, {%4,%5,%6,%7}, {%8,%9}, {%0,%1,%2,%3};"
                    : "+f"(acc[t][0]), "+f"(acc[t][1]), "+f"(acc[t][2]), "+f"(acc[t][3])
                    : "r"(a0), "r"(a1), "r"(a2), "r"(a3), "r"(b0), "r"(b1));
            }
        }
        __syncthreads();
    }

    const int r0 = rowbase + wid * 16 + lane / 4;
    const int r1 = r0 + 8;
    const int cb = (lane & 3) * 2;
#pragma unroll
    for (int t = 0; t < 20; t++) {
        int col = t * 8 + cb;
        float* base = (col < 80) ? outA : outB;
        int cc = (col < 80) ? col : col - 80;
        float bia0 = s_bias[col], bia1 = s_bias[col + 1];
        if (r0 < NNODES)
            *(float2*)(base + (size_t)r0 * 80 + cc) =
                make_float2(acc[t][0] + bia0, acc[t][1] + bia1);
        if (r1 < NNODES)
            *(float2*)(base + (size_t)r1 * 80 + cc) =
                make_float2(acc[t][2] + bia0, acc[t][3] + bia1);
    }
}

// ----- small GEMMs on tensor cores: BN+lrelu fused, bf16-split, K pad 48 ----
// A: [128 rows][96: hi k0-47 | lo k0-47] stride 104; B: [96 rows: hi|lo][80] stride 88.
#define SMA_STR 104
#define SMB_STR 88

__global__ void __launch_bounds__(256)
gemm_small3_mma(const float* __restrict__ preA, const float* __restrict__ preB,
                const float* __restrict__ stX, const float* __restrict__ stY,
                const float* __restrict__ g1, const float* __restrict__ be1,
                const float* __restrict__ g2, const float* __restrict__ be2,
                const float* __restrict__ Wc3, const float* __restrict__ bc3,
                float* __restrict__ outC,
                const float* __restrict__ Wc1, const float* __restrict__ bc1,
                float* __restrict__ outA,
                const float* __restrict__ Wc2, const float* __restrict__ bc2,
                float* __restrict__ outB,
                int nsets,
                const float* __restrict__ bnPre, const float* __restrict__ bnStats,
                const float* __restrict__ bnG, const float* __restrict__ bnB,
                float* __restrict__ bnDst, int bnOff) {
    const int bnStart = nsets * GB_SM;
    if ((int)blockIdx.x >= bnStart) {
        int idx = (blockIdx.x - bnStart) * 256 + threadIdx.x;
        if (idx >= NNODES * 20) return;
        int n = idx / 20, c = idx % 20;
        const float invN = 1.f / (float)NNODES;
        float mu = bnStats[c] * invN;
        float var = bnStats[20 + c] * invN - mu * mu;
        float scv = bnG[c] * rsqrtf(var + EPS_BN);
        float v = (bnPre[idx] - mu) * scv + bnB[c];
        v = (v >= 0.f) ? v : LSLOPE * v;
        bnDst[(size_t)n * 100 + bnOff + c] = v;
        return;
    }
    const int set = blockIdx.x / GB_SM;
    const int bi = blockIdx.x - set * GB_SM;
    const bool swap = (set == 2);
    const float* preX = swap ? preB : preA;
    const float* preY = swap ? preA : preB;
    const float* statsX = swap ? stY : stX;
    const float* statsY = swap ? stX : stY;
    const float* gX = swap ? g2 : g1;
    const float* betX = swap ? be2 : be1;
    const float* gY = swap ? g1 : g2;
    const float* betY = swap ? be1 : be2;
    const float* W = (set == 0) ? Wc3 : ((set == 1) ? Wc1 : Wc2);
    const float* b = (set == 0) ? bc3 : ((set == 1) ? bc1 : bc2);
    float* out = (set == 0) ? outC : ((set == 1) ? outA : outB);

    __shared__ __align__(16) __nv_bfloat16 sA[128][SMA_STR];
    __shared__ __align__(16) __nv_bfloat16 sB[96][SMB_STR];
    __shared__ float sMu[40], sScv[40], sBeta[40], sb2[80];

    const int tid = threadIdx.x, wid = tid >> 5, lane = tid & 31;
    const int rowbase = bi * 128;

    // ---- phase 1: weights, bias, BN params, zero pads ----
    for (int l = tid; l < 3200; l += 256) {
        int s = l / 800, rem = l % 800, k = rem / 20, o = rem % 20;
        float w = W[l];
        __nv_bfloat16 h = __float2bfloat16(w);
        int col = qkvpos(s * 20 + o);
        sB[k][col] = h;
        sB[48 + k][col] = __float2bfloat16(w - __bfloat162float(h));
    }
    if (tid < 80) sb2[qkvpos(tid)] = b[tid];
    if (tid < 40) {
        const float invN = 1.f / (float)NNODES;
        int c = tid % 20;
        const float* st = (tid < 20) ? statsX : statsY;
        const float* gg = (tid < 20) ? gX : gY;
        const float* bb = (tid < 20) ? betX : betY;
        float mu = st[c] * invN;
        float var = st[20 + c] * invN - mu * mu;
        sMu[tid] = mu;
        sScv[tid] = gg[c] * rsqrtf(var + EPS_BN);
        sBeta[tid] = bb[c];
    }
    // zero A pad cols (40-47, 88-95) : 128 rows x 8 u32
    for (int l = tid; l < 1024; l += 256) {
        int r = l >> 3, cp = l & 7;
        int col = (cp < 4) ? (40 + 2 * cp) : (88 + 2 * (cp - 4));
        *(uint32_t*)&sA[r][col] = 0u;
    }
    // zero B pad rows (40-47, 88-95): 16 rows x 44 u32
    for (int l = tid; l < 704; l += 256) {
        int rr = l / 44, c2 = l % 44;
        int row = (rr < 8) ? (40 + rr) : (80 + rr);
        *(uint32_t*)&sB[row][2 * c2] = 0u;
    }
    __syncthreads();

    // ---- phase 2: stage A = bf16-split(lrelu(BN(cat))) ----
    {
        int r = tid >> 1, h = tid & 1;
        int row = rowbase + r;
        const float* src = (h ? preY : preX) + (size_t)row * 20;
#pragma unroll
        for (int i = 0; i < 5; i++) {
            float4 v = (row < NNODES) ? *(const float4*)(src + 4 * i)
                                      : make_float4(0.f, 0.f, 0.f, 0.f);
            float vv[4] = {v.x, v.y, v.z, v.w};
#pragma unroll
            for (int j = 0; j < 4; j++) {
                int kk = h * 20 + 4 * i + j;
                float t = (vv[j] - sMu[kk]) * sScv[kk] + sBeta[kk];
                vv[j] = (t >= 0.f) ? t : LSLOPE * t;
            }
            float l0, l1, l2, l3;
            uint32_t h0 = packbf2(vv[0], vv[1], &l0, &l1);
            uint32_t h1 = packbf2(vv[2], vv[3], &l2, &l3);
            int col = h * 20 + 4 * i;
            *(uint32_t*)&sA[r][col] = h0;
            *(uint32_t*)&sA[r][col + 2] = h1;
            *(uint32_t*)&sA[r][48 + col] = packbf2s(l0, l1);
            *(uint32_t*)&sA[r][48 + col + 2] = packbf2s(l2, l3);
        }
    }
    __syncthreads();

    // ---- compute: 4 B-paired ksteps + 1 single, 10 n-tiles ----
    float acc[10][4];
#pragma unroll
    for (int t = 0; t < 10; t++)
#pragma unroll
        for (int i = 0; i < 4; i++) acc[t][i] = 0.f;

    const int r_in = lane & 7, blkb = (lane >> 3) & 1, kh = (lane >> 4) & 1;
    const uint32_t aBase =
        smem_u32(sA) + (uint32_t)((wid * 16 + blkb * 8 + r_in) * SMA_STR + kh * 8) * 2;
    const uint32_t bBase2 = smem_u32(sB) + (uint32_t)((lane & 15) * SMB_STR) * 2;
    const uint32_t bBase4 = smem_u32(sB) + (uint32_t)(lane * SMB_STR) * 2;

    const int browp[4] = {0, 32, 64, 0};
    const int a0p[4] = {0, 32, 16, 48};
    const int a1p[4] = {16, 0, 32, 64};

#pragma unroll
    for (int jp = 0; jp < 4; jp++) {
        uint32_t a0, a1, a2, a3, c0, c1, c2, c3;
        asm volatile(
            "ldmatrix.sync.aligned.m8n8.x4.shared.b16 {%0,%1,%2,%3}, [%4];"
            : "=r"(a0), "=r"(a1), "=r"(a2), "=r"(a3)
            : "r"(aBase + (uint32_t)a0p[jp] * 2));
        asm volatile(
            "ldmatrix.sync.aligned.m8n8.x4.shared.b16 {%0,%1,%2,%3}, [%4];"
            : "=r"(c0), "=r"(c1), "=r"(c2), "=r"(c3)
            : "r"(aBase + (uint32_t)a1p[jp] * 2));
        const uint32_t bb = bBase4 + (uint32_t)(browp[jp] * SMB_STR) * 2;
#pragma unroll
        for (int t = 0; t < 10; t++) {
            uint32_t b0, b1, b2, b3;
            asm volatile(
                "ldmatrix.sync.aligned.m8n8.x4.trans.shared.b16 {%0,%1,%2,%3}, [%4];"
                : "=r"(b0), "=r"(b1), "=r"(b2), "=r"(b3)
                : "r"(bb + (uint32_t)t * 16));
            asm volatile(
                "mma.sync.aligned.m16n8k16.row.col.f32.bf16.bf16.f32 "
                "{%0,%1,%2,%3}, {%4,%5,%6,%7}, {%8,%9}, {%0,%1,%2,%3};"
                : "+f"(acc[t][0]), "+f"(acc[t][1]), "+f"(acc[t][2]), "+f"(acc[t][3])
                : "r"(a0), "r"(a1), "r"(a2), "r"(a3), "r"(b0), "r"(b1));
            asm volatile(
                "mma.sync.aligned.m16n8k16.row.col.f32.bf16.bf16.f32 "
                "{%0,%1,%2,%3}, {%4,%5,%6,%7}, {%8,%9}, {%0,%1,%2,%3};"
                : "+f"(acc[t][0]), "+f"(acc[t][1]), "+f"(acc[t][2]), "+f"(acc[t][3])
                : "r"(c0), "r"(c1), "r"(c2), "r"(c3), "r"(b2), "r"(b3));
        }
    }
    {   // single kstep: A lo k32-47 x B hi k32-47
        uint32_t a0, a1, a2, a3;
        asm volatile(
            "ldmatrix.sync.aligned.m8n8.x4.shared.b16 {%0,%1,%2,%3}, [%4];"
            : "=r"(a0), "=r"(a1), "=r"(a2), "=r"(a3)
            : "r"(aBase + 80u * 2));
        const uint32_t bb = bBase2 + (uint32_t)(32 * SMB_STR) * 2;
#pragma unroll
        for (int t = 0; t < 10; t++) {
            uint32_t b0, b1;
            asm volatile(
                "ldmatrix.sync.aligned.m8n8.x2.trans.shared.b16 {%0,%1}, [%2];"
                : "=r"(b0), "=r"(b1)
                : "r"(bb + (uint32_t)t * 16));
            asm volatile(
                "mma.sync.aligned.m16n8k16.row.col.f32.bf16.bf16.f32 "
                "{%0,%1,%2,%3}, {%4,%5,%6,%7}, {%8,%9}, {%0,%1,%2,%3};"
                : "+f"(acc[t][0]), "+f"(acc[t][1]), "+f"(acc[t][2]), "+f"(acc[t][3])
                : "r"(a0), "r"(a1), "r"(a2), "r"(a3), "r"(b0), "r"(b1));
        }
    }

    // ---- epilogue ----
    const int r0 = rowbase + wid * 16 + lane / 4;
    const int r1 = r0 + 8;
    const int cb = (lane & 3) * 2;
#pragma unroll
    for (int t = 0; t < 10; t++) {
        int col = t * 8 + cb;
        float bia0 = sb2[col], bia1 = sb2[col + 1];
        if (r0 < NNODES)
            *(float2*)(out + (size_t)r0 * 80 + col) =
                make_float2(acc[t][0] + bia0, acc[t][1] + bia1);
        if (r1 < NNODES)
            *(float2*)(out + (size_t)r1 * 80 + col) =
                make_float2(acc[t][2] + bia0, acc[t][3] + bia1);
    }
}

// ---------- CSR aggregation: channel-pair lanes, 2 edges per warp-step ------
__global__ void __launch_bounds__(256)
agg_csr3(const float* __restrict__ q0, int nb0, float* __restrict__ p0, float* __restrict__ s0,
         const float* __restrict__ q1, int nb1, float* __restrict__ p1, float* __restrict__ s1,
         const float* __restrict__ q2, int nb2, float* __restrict__ p2, float* __restrict__ s2) {
    const int set = blockIdx.x / GA_BLK;
    const int bi = blockIdx.x - set * GA_BLK;
    const float* qkv = (set == 0) ? q0 : ((set == 1) ? q1 : q2);
    float* pre = (set == 0) ? p0 : ((set == 1) ? p1 : p2);
    float* stats = (set == 0) ? s0 : ((set == 1) ? s1 : s2);
    const int nbase = (set == 0) ? nb0 : ((set == 1) ? nb1 : nb2);

    const int wid = threadIdx.x >> 5, lane = threadIdx.x & 31;
    const int n = bi * 8 + wid;
    const int half = lane >> 4;
    const int hl = lane & 15;
    const bool act = hl < 10;
    const int cp = hl;

    __shared__ float sst[2][8][20];
    for (int l = threadIdx.x; l < 320; l += 256) ((float*)sst)[l] = 0.f;
    __syncthreads();

    if (n < NNODES) {
        const int gi = nbase + n;
        const int off0 = g_off[gi], off1 = g_off[gi + 1];
        float2 q2v = make_float2(0.f, 0.f);
        if (act) {
            q2v = *(const float2*)(qkv + (size_t)n * 80 + 2 * cp);
            q2v.x *= 0.22360679774997896f;
            q2v.y *= 0.22360679774997896f;
        }
        const uint32_t kvf = 20 + 4 * cp;
        float accx = 0.f, accy = 0.f, denom = 0.f;
        int p = off0;
        for (; p + 4 <= off1; p += 4) {
            int sA = g_csr[p + half];
            int sB = g_csr[p + 2 + half];
            float4 kv0 = act ? *(const float4*)(qkv + (size_t)sA * 80 + kvf)
                             : make_float4(0.f, 0.f, 0.f, 0.f);
            float4 kv1 = act ? *(const float4*)(qkv + (size_t)sB * 80 + kvf)
                             : make_float4(0.f, 0.f, 0.f, 0.f);
            float d0 = q2v.x * kv0.x + q2v.y * kv0.z;
            float d1 = q2v.x * kv1.x + q2v.y * kv1.z;
#pragma unroll
            for (int o = 8; o; o >>= 1) {
                d0 += __shfl_xor_sync(~0u, d0, o);
                d1 += __shfl_xor_sync(~0u, d1, o);
            }
            float e0 = __expf(d0), e1 = __expf(d1);
            denom += e0 + e1;
            accx += e0 * kv0.y + e1 * kv1.y;
            accy += e0 * kv0.w + e1 * kv1.w;
        }
        for (; p < off1; p += 2) {
            bool ea = (p + half) < off1;
            int sA = ea ? g_csr[p + half] : 0;
            float4 kv0 = (act && ea) ? *(const float4*)(qkv + (size_t)sA * 80 + kvf)
                                     : make_float4(0.f, 0.f, 0.f, 0.f);
            float d0 = q2v.x * kv0.x + q2v.y * kv0.z;
#pragma unroll
            for (int o = 8; o; o >>= 1) d0 += __shfl_xor_sync(~0u, d0, o);
            float e0 = ea ? __expf(d0) : 0.f;
            denom += e0;
            accx += e0 * kv0.y;
            accy += e0 * kv0.w;
        }
        accx += __shfl_xor_sync(~0u, accx, 16);
        accy += __shfl_xor_sync(~0u, accy, 16);
        denom += __shfl_xor_sync(~0u, denom, 16);
        float inv = 1.f / fmaxf(denom, 1e-16f);
        if (act && half == 0) {
            float2 sk = *(const float2*)(qkv + (size_t)n * 80 + 60 + 2 * cp);
            float rx = accx * inv + sk.x;
            float ry = accy * inv + sk.y;
            *(float2*)(pre + (size_t)n * 20 + 2 * cp) = make_float2(rx, ry);
            sst[0][wid][2 * cp] = rx;
            sst[0][wid][2 * cp + 1] = ry;
            sst[1][wid][2 * cp] = rx * rx;
            sst[1][wid][2 * cp + 1] = ry * ry;
        }
    }
    __syncthreads();
    if (threadIdx.x < 40) {
        int which = threadIdx.x / 20, cc = threadIdx.x % 20;
        float t = 0.f;
#pragma unroll
        for (int w = 0; w < 8; w++) t += sst[which][w][cc];
        atomicAdd(&stats[which * 20 + cc], t);
    }
}

// ------------- final FC with fused last-layer BN (cols 80..99 inline) ------
__global__ void __launch_bounds__(128)
fc_bn_kernel(const float* __restrict__ W, const float* __restrict__ b,
             const float* __restrict__ preC, const float* __restrict__ stats,
             const float* __restrict__ gamma, const float* __restrict__ beta,
             float* __restrict__ out) {
    __shared__ float sw[200];
    __shared__ float sMu[20], sScv[20], sBeta[20];
    for (int l = threadIdx.x; l < 200; l += blockDim.x) sw[l] = W[l];
    if (threadIdx.x < 20) {
        const float invN = 1.f / (float)NNODES;
        int c = threadIdx.x;
        float mu = stats[c] * invN;
        float var = stats[20 + c] * invN - mu * mu;
        sMu[c] = mu;
        sScv[c] = gamma[c] * rsqrtf(var + EPS_BN);
        sBeta[c] = beta[c];
    }
    __syncthreads();
    int n = blockIdx.x * blockDim.x + threadIdx.x;
    if (n >= NNODES) return;
    float a0 = b[0], a1 = b[1];
    const float4* fp = (const float4*)(g_fc + (size_t)n * 100);
#pragma unroll
    for (int i = 0; i < 20; i++) {
        float4 f = fp[i];
        int c = 4 * i;
        a0 += f.x * sw[2 * c] + f.y * sw[2 * c + 2] + f.z * sw[2 * c + 4] + f.w * sw[2 * c + 6];
        a1 += f.x * sw[2 * c + 1] + f.y * sw[2 * c + 3] + f.z * sw[2 * c + 5] + f.w * sw[2 * c + 7];
    }
    const float4* pp = (const float4*)(preC + (size_t)n * 20);
#pragma unroll
    for (int i = 0; i < 5; i++) {
        float4 f = pp[i];
        float vv[4] = {f.x, f.y, f.z, f.w};
#pragma unroll
        for (int j = 0; j < 4; j++) {
            int c = 4 * i + j;
            float v = (vv[j] - sMu[c]) * sScv[c] + sBeta[c];
            v = (v >= 0.f) ? v : LSLOPE * v;
            int col = 80 + c;
            a0 += v * sw[2 * col];
            a1 += v * sw[2 * col + 1];
        }
    }
    out[2 * n] = a0;
    out[2 * n + 1] = a1;
}

// ------------------------- host orchestration -------------------------
extern "C" void kernel_launch(void* const* d_in, const int* in_sizes, int n_in,
                              void* d_out, int out_size) {
    (void)in_sizes; (void)n_in; (void)out_size;
    const float* features = (const float*)d_in[0];
    const int* edge_index = (const int*)d_in[3];
    const int* same2      = (const int*)d_in[4];
    const int* diff2      = (const int*)d_in[5];
    const float* c1_W0 = (const float*)d_in[6];
    const float* c1_b0 = (const float*)d_in[7];
    const float* c2_W0 = (const float*)d_in[8];
    const float* c2_b0 = (const float*)d_in[9];
    const float* c1_W  = (const float*)d_in[10];
    const float* c1_b  = (const float*)d_in[11];
    const float* c2_W  = (const float*)d_in[12];
    const float* c2_b  = (const float*)d_in[13];
    const float* c3_W  = (const float*)d_in[14];
    const float* c3_b  = (const float*)d_in[15];
    const float* bn1_g = (const float*)d_in[16];
    const float* bn1_b = (const float*)d_in[17];
    const float* bn2_g = (const float*)d_in[18];
    const float* bn2_b = (const float*)d_in[19];
    const float* bn3_g = (const float*)d_in[20];
    const float* bn3_b = (const float*)d_in[21];
    const float* fc_W  = (const float*)d_in[22];
    const float* fc_b  = (const float*)d_in[23];
    float* out = (float*)d_out;

    float *qkvA, *qkvB, *qkvC, *preA, *preB, *preC, *fcb, *stats;
    cudaGetSymbolAddress((void**)&qkvA, g_qkvA);
    cudaGetSymbolAddress((void**)&qkvB, g_qkvB);
    cudaGetSymbolAddress((void**)&qkvC, g_qkvC);
    cudaGetSymbolAddress((void**)&preA, g_preA);
    cudaGetSymbolAddress((void**)&preB, g_preB);
    cudaGetSymbolAddress((void**)&preC, g_preC);
    cudaGetSymbolAddress((void**)&fcb, g_fc);
    cudaGetSymbolAddress((void**)&stats, g_stats);

    const int G3E = (3 * NEDGE + 255) / 256;

    cudaFuncSetAttribute(gemm_big_mma, cudaFuncAttributeMaxDynamicSharedMemorySize,
                         SMEM_MMA);

    static cudaStream_t s2 = nullptr;
    static cudaEvent_t evFork = nullptr, evJoin = nullptr;
    if (!s2) {
        cudaStreamCreateWithFlags(&s2, cudaStreamNonBlocking);
        cudaEventCreateWithFlags(&evFork, cudaEventDisableTiming);
        cudaEventCreateWithFlags(&evJoin, cudaEventDisableTiming);
    }

    // ---- fork: CSR build on s2, conv_w + big GEMM on default ----
    cudaEventRecord(evFork, 0);
    cudaStreamWaitEvent(s2, evFork, 0);

    zero_all<<<(NN3 + 255) / 256, 256, 0, s2>>>();
    hist_kernel<<<G3E, 256, 0, s2>>>(same2, diff2, edge_index);
    scanA<<<SCAN_BLOCKS, 1024, 0, s2>>>();
    scanB<<<1, 256, 0, s2>>>();
    scanC<<<SCAN_BLOCKS, 1024, 0, s2>>>();
    scatter_kernel<<<G3E, 256, 0, s2>>>(same2, diff2, edge_index);
    cudaEventRecord(evJoin, s2);

    conv_w<<<(2000 * 160 + 255) / 256, 256>>>(c1_W0, c2_W0);
    gemm_big_mma<<<GB_SM, 256, SMEM_MMA>>>(features, c1_b0, c2_b0, qkvA, qkvB);

    cudaStreamWaitEvent(0, evJoin, 0);

    // ---- layer 0 ----
    agg_csr3<<<2 * GA_BLK, 256>>>(qkvA, 0, preA, stats + 0 * 40,
                                  qkvB, NNODES, preB, stats + 1 * 40,
                                  qkvA, 0, preA, stats + 0 * 40);

    for (int L = 0; L <= 4; L++) {
        const float* stX = stats + (3 * L) * 40;
        const float* stY = stats + (3 * L + 1) * 40;
        const float* g1 = bn1_g + L * 20; const float* b1 = bn1_b + L * 20;
        const float* g2 = bn2_g + L * 20; const float* b2 = bn2_b + L * 20;
        const int nsets = (L < 4) ? 3 : 1;
        const int bnBlocks = (L > 0) ? GN_BLK : 0;

        gemm_small3_mma<<<nsets * GB_SM + bnBlocks, 256>>>(
            preA, preB, stX, stY, g1, b1, g2, b2,
            c3_W + (size_t)L * 3200, c3_b + (size_t)L * 80, qkvC,
            c1_W + (size_t)L * 3200, c1_b + (size_t)L * 80, qkvA,
            c2_W + (size_t)L * 3200, c2_b + (size_t)L * 80, qkvB,
            nsets,
            preC, stats + (3 * (L - 1) + 2) * 40,
            bn3_g + (L - 1) * 20, bn3_b + (L - 1) * 20, fcb, (L - 1) * 20);

        if (L < 4) {
            agg_csr3<<<3 * GA_BLK, 256>>>(qkvC, 2 * NNODES, preC, stats + (3 * L + 2) * 40,
                                          qkvA, 0, preA, stats + (3 * L + 3) * 40,
                                          qkvB, NNODES, preB, stats + (3 * L + 4) * 40);
        } else {
            agg_csr3<<<GA_BLK, 256>>>(qkvC, 2 * NNODES, preC, stats + (3 * L + 2) * 40,
                                      qkvC, 2 * NNODES, preC, stats + (3 * L + 2) * 40,
                                      qkvC, 2 * NNODES, preC, stats + (3 * L + 2) * 40);
        }
    }

    fc_bn_kernel<<<(NNODES + 127) / 128, 128>>>(fc_W, fc_b, preC, stats + 14 * 40,
                                                bn3_g + 80, bn3_b + 80, out);
}